// round 10
// baseline (speedup 1.0000x reference)
#include <cuda_runtime.h>
#include <cuda_bf16.h>
#include <math.h>
#include <stdint.h>

#define Hq 32
#define KVH 8
#define HD 128
#define Bn 4
#define Sn 1024
#define DM 4096
#define KVD 1024
#define NTOK (Bn*Sn)
#define WINDOW 512

#if defined(__CUDA_ARCH_FEAT_SM103_ALL) || defined(__CUDA_ARCH_FEAT_SM100_ALL)
#define TC_FEAT 1
#else
#define TC_FEAT 0
#endif

// Scratch
__device__ float g_q[NTOK * DM];
__device__ float g_k[NTOK * KVD];
__device__ float g_v[NTOK * KVD];
__device__ __nv_bfloat16 g_a_hi[NTOK * DM];
__device__ __nv_bfloat16 g_a_lo[NTOK * DM];
// tile-major, pre-swizzled weights: [nblk][ktile][32KB tile]; row=[hi 64B|lo 64B]
__device__ __align__(128) unsigned char g_wq_t[(DM/256) * (DM/32) * 32768];
__device__ __align__(128) unsigned char g_wkv_t[(2*KVD/256) * (DM/32) * 32768];
__device__ __align__(128) unsigned char g_wo_t[(DM/256) * (DM/32) * 32768];
__device__ __nv_bfloat16 g_qs_hi[NTOK * DM];
__device__ __nv_bfloat16 g_qs_lo[NTOK * DM];
__device__ __nv_bfloat16 g_ks_hi[NTOK * KVD];
__device__ __nv_bfloat16 g_ks_lo[NTOK * KVD];
__device__ __nv_bfloat16 g_vt_hi[NTOK * KVD];
__device__ __nv_bfloat16 g_vt_lo[NTOK * KVD];
__device__ __nv_bfloat16 g_o_hi[NTOK * DM];
__device__ __nv_bfloat16 g_o_lo[NTOK * DM];

__device__ __forceinline__ uint32_t smem_u32(const void* p) {
    uint32_t a;
    asm("{ .reg .u64 t; cvta.to.shared.u64 t, %1; cvt.u32.u64 %0, t; }"
        : "=r"(a) : "l"(p));
    return a;
}
__device__ __forceinline__ uint32_t elect_one() {
    uint32_t pred;
    asm volatile("{\n .reg .pred p;\n elect.sync _|p, 0xFFFFFFFF;\n"
                 " selp.b32 %0, 1, 0, p;\n}" : "=r"(pred));
    return pred;
}
__device__ __forceinline__ uint32_t cluster_rank() {
    uint32_t r;
    asm("mov.u32 %0, %%cluster_ctarank;" : "=r"(r));
    return r;
}
#define CLUSTER_SYNC() do { \
    asm volatile("barrier.cluster.arrive.aligned;" ::: "memory"); \
    asm volatile("barrier.cluster.wait.aligned;" ::: "memory"); } while (0)

#define SMEM_SW128(off) ((off) ^ (((off) >> 3) & 0x70))
static constexpr uint64_t DESC_BASE_SW128 =
    (uint64_t(2) << 61) | (uint64_t(1) << 46) | (uint64_t(64) << 32) |
    (uint64_t(1) << 16);
__device__ __forceinline__ uint64_t make_desc(uint32_t addr) {
    return DESC_BASE_SW128 | ((uint64_t)(addr >> 4) & 0x3FFF);
}
#define MBAR_INIT(a, n) \
    asm volatile("mbarrier.init.shared.b64 [%0], %1;" :: "r"(a), "r"(n) : "memory")
#define MBAR_INVAL(a) \
    asm volatile("mbarrier.inval.shared.b64 [%0];" :: "r"(a) : "memory")
#define MBAR_EXPECT_TX(a, n) \
    asm volatile("mbarrier.arrive.expect_tx.shared.b64 _, [%0], %1;" \
                 :: "r"(a), "r"((uint32_t)(n)) : "memory")
#define MBAR_ARRIVE_RANK(a, r) \
    asm volatile("{\n\t.reg .b32 ra;\n\tmapa.shared::cluster.u32 ra, %0, %1;\n\t" \
                 "mbarrier.arrive.shared::cluster.b64 _, [ra];\n\t}" \
                 :: "r"(a), "r"((uint32_t)(r)) : "memory")
// 1D bulk copy global->shared, multicast to cluster CTAs in mask
#define BULK_MC(dst, src, bytes, mbar, mask) \
    asm volatile("cp.async.bulk.shared::cluster.global.mbarrier::complete_tx::bytes" \
                 ".multicast::cluster [%0], [%1], %2, [%3], %4;" \
                 :: "r"(dst), "l"(src), "r"((uint32_t)(bytes)), "r"(mbar), \
                    "h"((uint16_t)(mask)) : "memory")

__device__ __forceinline__ void mbar_wait(uint32_t mbar, uint32_t parity) {
    uint32_t done;
    asm volatile("{\n\t.reg .pred p;\n\t"
        "mbarrier.try_wait.parity.acquire.cta.shared::cta.b64 p, [%1], %2;\n\t"
        "selp.b32 %0, 1, 0, p;\n\t}" : "=r"(done) : "r"(mbar), "r"(parity) : "memory");
    while (!done) {
        asm volatile("{\n\t.reg .pred p;\n\t"
            "mbarrier.try_wait.parity.acquire.cta.shared::cta.b64 p, [%1], %2, 0x989680;\n\t"
            "selp.b32 %0, 1, 0, p;\n\t}" : "=r"(done) : "r"(mbar), "r"(parity) : "memory");
    }
}
#define CP_ASYNC16(dst, src) \
    asm volatile("cp.async.cg.shared.global [%0], [%1], 16;" :: "r"(dst), "l"(src))
#define CP_COMMIT() asm volatile("cp.async.commit_group;" ::: "memory")
#define CP_WAIT0()  asm volatile("cp.async.wait_group 0;" ::: "memory")
#define CP_WAIT1()  asm volatile("cp.async.wait_group 1;" ::: "memory")

#if TC_FEAT
__device__ __forceinline__ void mma_bf16_ss(
    uint32_t d_tmem, uint64_t a_desc, uint64_t b_desc, uint32_t idesc, bool acc)
{
    uint32_t en = acc ? 1u : 0u;
    asm volatile(
        "{\n\t.reg .pred p;\n\tsetp.ne.u32 p, %4, 0;\n\t"
        "tcgen05.mma.cta_group::1.kind::f16 [%0], %1, %2, %3, {%5,%5,%5,%5}, p;\n\t}"
        :: "r"(d_tmem), "l"(a_desc), "l"(b_desc), "r"(idesc), "r"(en), "r"(0u)
        : "memory");
}
#define TC_ALLOC(a, n) \
    asm volatile("tcgen05.alloc.cta_group::1.sync.aligned.shared::cta.b32 [%0], %1;" \
                 :: "r"(a), "r"((uint32_t)(n)) : "memory")
#define TC_DEALLOC(t, n) \
    asm volatile("tcgen05.dealloc.cta_group::1.sync.aligned.b32 %0, %1;" \
                 :: "r"(t), "r"((uint32_t)(n)))
#define TC_RELINQ() \
    asm volatile("tcgen05.relinquish_alloc_permit.cta_group::1.sync.aligned;")
#define TC_COMMIT(m) \
    asm volatile("tcgen05.commit.cta_group::1.mbarrier::arrive::one.shared::cluster.b64 [%0];" \
                 :: "r"(m) : "memory")
#define TC_FENCE_AFTER() asm volatile("tcgen05.fence::after_thread_sync;" ::: "memory")
#define FENCE_ASYNC_SHARED() asm volatile("fence.proxy.async.shared::cta;" ::: "memory")
#define TC_LD_X32(r, addr) \
    asm volatile("tcgen05.ld.sync.aligned.32x32b.x32.b32 " \
        "{%0,%1,%2,%3,%4,%5,%6,%7,%8,%9,%10,%11,%12,%13,%14,%15," \
        "%16,%17,%18,%19,%20,%21,%22,%23,%24,%25,%26,%27,%28,%29,%30,%31}, [%32];" \
        : "=r"((r)[0]), "=r"((r)[1]), "=r"((r)[2]), "=r"((r)[3]), \
          "=r"((r)[4]), "=r"((r)[5]), "=r"((r)[6]), "=r"((r)[7]), \
          "=r"((r)[8]), "=r"((r)[9]), "=r"((r)[10]), "=r"((r)[11]), \
          "=r"((r)[12]), "=r"((r)[13]), "=r"((r)[14]), "=r"((r)[15]), \
          "=r"((r)[16]), "=r"((r)[17]), "=r"((r)[18]), "=r"((r)[19]), \
          "=r"((r)[20]), "=r"((r)[21]), "=r"((r)[22]), "=r"((r)[23]), \
          "=r"((r)[24]), "=r"((r)[25]), "=r"((r)[26]), "=r"((r)[27]), \
          "=r"((r)[28]), "=r"((r)[29]), "=r"((r)[30]), "=r"((r)[31]) \
        : "r"(addr))
#define TC_WAIT_LD() asm volatile("tcgen05.wait::ld.sync.aligned;" ::: "memory")
#endif

// ---------------------------------------------------------------------------
// tcgen05 GEMM, 256x256 CTA tile, K-tile 32, 3 stages.
// A (activations, row-major hi/lo) via cp.async. B (weights, tile-major
// pre-swizzled) via 1D bulk multicast across a (1,2,1) cluster: CTA pairs
// share blockIdx.x (same weights), each loads a 16KB slice, multicast both.
// ---------------------------------------------------------------------------
#define GS_STAGE  65536
#define GS_B_OFF  32768
#define GS_M_MMA  196608
#define GS_M_FULL 196640
#define GS_M_EMPT 196672
#define GS_TPTR   196704
#define GS_DYN    (196736 + 1024)
#define G_IDESC   ((1u<<4)|(1u<<7)|(1u<<10)|(32u<<17)|(8u<<24))   // N=256

__global__ __cluster_dims__(1, 2, 1) __launch_bounds__(256, 1) void tc_gemm2(
    const __nv_bfloat16* __restrict__ Ahi, const __nv_bfloat16* __restrict__ Alo,
    const unsigned char* __restrict__ Bt,
    float* __restrict__ C, float* __restrict__ C2, int ldc, int nsplit,
    int M, int N, int K)
{
#if TC_FEAT
    extern __shared__ char dsm[];
    char* smb = (char*)(((uintptr_t)dsm + 1023) & ~(uintptr_t)1023);
    const uint32_t smb_u = smem_u32(smb);
    const int tid = threadIdx.x;
    const int wid = tid >> 5;
    const int lane = tid & 31;
    const int m0 = blockIdx.y * 256;
    const int n0 = blockIdx.x * 256;
    const uint32_t rank = cluster_rank();

    if (wid == 0) TC_ALLOC(smb_u + GS_TPTR, 512);
    if (tid == 0) {
#pragma unroll
        for (int i = 0; i < 3; ++i) {
            MBAR_INIT(smb_u + GS_M_MMA + 8 * i, 1);
            MBAR_INIT(smb_u + GS_M_FULL + 8 * i, 1);
            MBAR_INIT(smb_u + GS_M_EMPT + 8 * i, 2);
        }
    }
    __syncthreads();
    CLUSTER_SYNC();
    uint32_t tmem;
    asm volatile("ld.shared.b32 %0, [%1];" : "=r"(tmem) : "r"(smb_u + GS_TPTR));

    const int T = K >> 5;
    auto stageA = [&](int t) {
        const uint32_t sbase = smb_u + (t % 3) * GS_STAGE;
        const int k0 = t * 32;
#pragma unroll
        for (int r = 0; r < 8; ++r) {
            int i = tid + r * 256;
            int row = i >> 3, c = i & 7;
            uint32_t dst = sbase + SMEM_SW128((uint32_t)(row * 128 + c * 16));
            const __nv_bfloat16* src = ((c & 4) ? Alo : Ahi)
                + (size_t)(m0 + row) * K + k0 + (c & 3) * 8;
            CP_ASYNC16(dst, src);
        }
        CP_COMMIT();
    };
    auto stageB = [&](int t) {   // tid0 only
        const int s = t % 3;
        MBAR_EXPECT_TX(smb_u + GS_M_FULL + 8 * s, 32768);
        const unsigned char* src = Bt +
            ((size_t)blockIdx.x * (K >> 5) + t) * 32768 + rank * 16384;
        uint32_t dst = smb_u + s * GS_STAGE + GS_B_OFF + rank * 16384;
        BULK_MC(dst, src, 16384, smb_u + GS_M_FULL + 8 * s, 3);
    };

    stageA(0); stageA(1);
    if (tid == 0) { stageB(0); stageB(1); }

    for (int t = 0; t < T; ++t) {
        if (t < T - 1) { CP_WAIT1(); } else { CP_WAIT0(); }
        FENCE_ASYNC_SHARED();
        __syncthreads();

        if (wid == 0 && elect_one()) {
            mbar_wait(smb_u + GS_M_FULL + 8 * (t % 3), (uint32_t)((t / 3) & 1));
            const uint32_t sbase = smb_u + (t % 3) * GS_STAGE;
            uint64_t da = make_desc(sbase);
            uint64_t db = make_desc(sbase + GS_B_OFF);
#pragma unroll
            for (int k = 0; k < 2; ++k)
#pragma unroll
                for (int m = 0; m < 2; ++m) {
                    uint32_t d = tmem + m * 256;
                    uint64_t ao = (uint64_t)(m * 1024);
                    bool first = (t == 0) && (k == 0);
                    mma_bf16_ss(d, da + ao + k * 2,     db + k * 2,     G_IDESC, !first);
                    mma_bf16_ss(d, da + ao + k * 2,     db + 4 + k * 2, G_IDESC, true);
                    mma_bf16_ss(d, da + ao + 4 + k * 2, db + k * 2,     G_IDESC, true);
                }
            TC_COMMIT(smb_u + GS_M_MMA + 8 * (t % 3));
        }

        if (t + 2 < T) {
            const int s = (t + 2) % 3;
            if (t >= 1)
                mbar_wait(smb_u + GS_M_MMA + 8 * s, (uint32_t)(((t - 1) / 3) & 1));
            stageA(t + 2);
            if (tid == 0) {
                if (t >= 1) {
                    MBAR_ARRIVE_RANK(smb_u + GS_M_EMPT + 8 * s, 0);
                    MBAR_ARRIVE_RANK(smb_u + GS_M_EMPT + 8 * s, 1);
                    mbar_wait(smb_u + GS_M_EMPT + 8 * s,
                              (uint32_t)((((t + 2) / 3) - 1) & 1));
                }
                stageB(t + 2);
            }
        }
    }
#pragma unroll
    for (int i = 0; i < 3; ++i) {
        int cnt = (T + 2 - i) / 3;
        if (cnt > 0)
            mbar_wait(smb_u + GS_M_MMA + 8 * i, (uint32_t)((cnt - 1) & 1));
    }
    TC_FENCE_AFTER();

    {
        const int half = wid >> 2;
        const int mloc = (wid & 3) * 32 + lane;
        float* base;
        int col;
        if (n0 < nsplit) { base = C; col = n0; }
        else             { base = C2; col = n0 - nsplit; }
        float* crow = base + (size_t)(m0 + half * 128 + mloc) * ldc + col;
        uint32_t regs[32];
#pragma unroll
        for (int c = 0; c < 8; ++c) {
            TC_LD_X32(regs, tmem + half * 256 + c * 32);
            TC_WAIT_LD();
#pragma unroll
            for (int i = 0; i < 8; ++i)
                *(float4*)(crow + c * 32 + 4 * i) = make_float4(
                    __uint_as_float(regs[4*i]), __uint_as_float(regs[4*i+1]),
                    __uint_as_float(regs[4*i+2]), __uint_as_float(regs[4*i+3]));
        }
    }
    __syncthreads();
    if (tid == 0) {
#pragma unroll
        for (int i = 0; i < 3; ++i) {
            MBAR_INVAL(smb_u + GS_M_MMA + 8 * i);
            MBAR_INVAL(smb_u + GS_M_FULL + 8 * i);
            MBAR_INVAL(smb_u + GS_M_EMPT + 8 * i);
        }
    }
    __syncthreads();
    if (wid == 0) { TC_RELINQ(); TC_DEALLOC(tmem, 512); }
    CLUSTER_SYNC();
#endif
}

// ---------------------------------------------------------------------------
// tcgen05 attention (unchanged from R8).
// ---------------------------------------------------------------------------
#define AT_Q     0
#define AT_KP    131072
#define AT_V     196608
#define AT_MBAR  229376
#define AT_TPTR  229408
#define AT_DYN   (229440 + 1024)
#define IDESC_S  ((1u<<4)|(1u<<7)|(1u<<10)|(8u<<17)|(8u<<24))
#define IDESC_O  ((1u<<4)|(1u<<7)|(1u<<10)|(16u<<17)|(8u<<24))
#define SMAX_C   12.0f

__global__ __launch_bounds__(256, 1) void tc_attn(
    const __nv_bfloat16* __restrict__ qsh, const __nv_bfloat16* __restrict__ qsl,
    const __nv_bfloat16* __restrict__ ksh, const __nv_bfloat16* __restrict__ ksl,
    const __nv_bfloat16* __restrict__ vth, const __nv_bfloat16* __restrict__ vtl,
    __nv_bfloat16* __restrict__ ohi, __nv_bfloat16* __restrict__ olo)
{
#if TC_FEAT
    extern __shared__ char dsm[];
    char* smb = (char*)(((uintptr_t)dsm + 1023) & ~(uintptr_t)1023);
    const uint32_t smb_u = smem_u32(smb);
    const uint32_t mbar_s = smb_u + AT_MBAR;
    const uint32_t mbar_o = smb_u + AT_MBAR + 8;
    const int tid = threadIdx.x;
    const int wid = tid >> 5;
    const int q0 = (int)(gridDim.x - 1 - blockIdx.x) * 64;
    const int kvh = blockIdx.y;
    const int b = blockIdx.z;
    const int bk = b * KVH + kvh;

    if (wid == 0) TC_ALLOC(smb_u + AT_TPTR, 512);
    if (tid == 0) { MBAR_INIT(mbar_s, 1); MBAR_INIT(mbar_o, 1); }
    __syncthreads();
    uint32_t tmem;
    asm volatile("ld.shared.b32 %0, [%1];" : "=r"(tmem) : "r"(smb_u + AT_TPTR));
    const uint32_t tmS = tmem;
    const uint32_t tmO = tmem + 128;

#pragma unroll
    for (int r = 0; r < 32; ++r) {
        int u = tid + r * 256;
        int row = u >> 5, cc = u & 31;
        int s = cc >> 4, hh = (cc >> 3) & 1, c = cc & 7;
        uint32_t byte = (uint32_t)(((row >> 3) + (s * 2 + hh) * 32) * 1024 +
                                   (row & 7) * 128 + c * 16);
        int tok = b * Sn + q0 + (row & 63);
        int head = kvh * 4 + (row >> 6);
        const __nv_bfloat16* src = (s ? qsl : qsh)
            + (size_t)tok * DM + head * HD + hh * 64 + c * 8;
        CP_ASYNC16(smb_u + AT_Q + SMEM_SW128(byte), src);
    }
    CP_COMMIT();

    const int kc0 = (q0 >= WINDOW) ? (q0 - WINDOW) : 0;
    const int nch = (q0 - kc0) / 64 + 1;
    float l_i = 0.f;
    uint32_t ps = 0, po = 0;
    const int atom = wid >> 2;
    const int grow = tid;
    const int qi = q0 + (grow & 63);

    for (int ci = 0; ci < nch; ++ci) {
        const int kc = kc0 + ci * 64;
        if (ci > 0) { mbar_wait(mbar_o, po); po ^= 1; }

#pragma unroll
        for (int r = 0; r < 8; ++r) {
            int u = tid + r * 256;
            int key = u >> 5, cc = u & 31;
            int s = cc >> 4, hh = (cc >> 3) & 1, c = cc & 7;
            uint32_t byte = (uint32_t)(((key >> 3) + (s * 2 + hh) * 8) * 1024 +
                                       (key & 7) * 128 + c * 16);
            const __nv_bfloat16* src = (s ? ksl : ksh)
                + (size_t)(b * Sn + kc + key) * KVD + kvh * HD + hh * 64 + c * 8;
            CP_ASYNC16(smb_u + AT_KP + SMEM_SW128(byte), src);
        }
        CP_COMMIT();
#pragma unroll
        for (int r = 0; r < 8; ++r) {
            int u = tid + r * 256;
            int d = u >> 4, cc = u & 15;
            int s = cc >> 3, c = cc & 7;
            uint32_t byte = (uint32_t)(((d >> 3) + s * 16) * 1024 +
                                       (d & 7) * 128 + c * 16);
            const __nv_bfloat16* src = (s ? vtl : vth)
                + (size_t)bk * HD * Sn + (size_t)d * Sn + kc + c * 8;
            CP_ASYNC16(smb_u + AT_V + SMEM_SW128(byte), src);
        }
        CP_COMMIT();
        CP_WAIT1();
        FENCE_ASYNC_SHARED();
        __syncthreads();

        if (wid == 0 && elect_one()) {
            uint64_t dq = make_desc(smb_u + AT_Q);
            uint64_t dk = make_desc(smb_u + AT_KP);
#pragma unroll
            for (int m = 0; m < 2; ++m)
#pragma unroll
                for (int pat = 0; pat < 3; ++pat) {
                    int sa = (pat == 2), sb = (pat == 1);
#pragma unroll
                    for (int k = 0; k < 8; ++k) {
                        uint64_t qo = (uint64_t)(m * 1024 +
                                      (sa * 2 + (k >> 2)) * 2048 + (k & 3) * 2);
                        uint64_t ko = (uint64_t)((sb * 2 + (k >> 2)) * 512 + (k & 3) * 2);
                        mma_bf16_ss(tmS + m * 64, dq + qo, dk + ko, IDESC_S,
                                    !(pat == 0 && k == 0));
                    }
                }
            TC_COMMIT(mbar_s);
        }

        mbar_wait(mbar_s, ps);
        ps ^= 1;
        TC_FENCE_AFTER();
        uint32_t su[64];
        TC_LD_X32(su, tmS + atom * 64);
        TC_LD_X32(su + 32, tmS + atom * 64 + 32);
        TC_WAIT_LD();
        float l_add = 0.f;
#pragma unroll
        for (int c16 = 0; c16 < 8; ++c16) {
            uint32_t wh[4], wl[4];
#pragma unroll
            for (int e = 0; e < 4; ++e) {
                int i0 = c16 * 8 + e * 2;
                int j0 = kc + i0;
                float s0 = __uint_as_float(su[i0]);
                float s1 = __uint_as_float(su[i0 + 1]);
                float p0 = ((j0 <= qi) && (j0 > qi - WINDOW)) ? __expf(s0 - SMAX_C) : 0.f;
                float p1 = ((j0+1 <= qi) && (j0+1 > qi - WINDOW)) ? __expf(s1 - SMAX_C) : 0.f;
                l_add += p0 + p1;
                __nv_bfloat16 h0 = __float2bfloat16_rn(p0);
                __nv_bfloat16 h1 = __float2bfloat16_rn(p1);
                __nv_bfloat16 l0 = __float2bfloat16_rn(p0 - __bfloat162float(h0));
                __nv_bfloat16 l1 = __float2bfloat16_rn(p1 - __bfloat162float(h1));
                wh[e] = ((uint32_t)__bfloat16_as_ushort(h1) << 16) |
                        (uint32_t)__bfloat16_as_ushort(h0);
                wl[e] = ((uint32_t)__bfloat16_as_ushort(l1) << 16) |
                        (uint32_t)__bfloat16_as_ushort(l0);
            }
            uint32_t bh = (uint32_t)((grow >> 3) * 1024 + (grow & 7) * 128 + c16 * 16);
            uint32_t bl = bh + 32 * 1024;
            *(uint4*)(smb + AT_KP + SMEM_SW128(bh)) = make_uint4(wh[0], wh[1], wh[2], wh[3]);
            *(uint4*)(smb + AT_KP + SMEM_SW128(bl)) = make_uint4(wl[0], wl[1], wl[2], wl[3]);
        }
        l_i += l_add;
        CP_WAIT0();
        FENCE_ASYNC_SHARED();
        __syncthreads();

        if (wid == 0 && elect_one()) {
            uint64_t dp = make_desc(smb_u + AT_KP);
            uint64_t dv = make_desc(smb_u + AT_V);
#pragma unroll
            for (int m = 0; m < 2; ++m)
#pragma unroll
                for (int pat = 0; pat < 3; ++pat) {
                    int sp = (pat == 2), sv = (pat == 1);
#pragma unroll
                    for (int k = 0; k < 4; ++k) {
                        uint64_t pofs = (uint64_t)(m * 1024 + sp * 2048 + k * 2);
                        uint64_t vofs = (uint64_t)(sv * 1024 + k * 2);
                        mma_bf16_ss(tmO + m * 128, dp + pofs, dv + vofs, IDESC_O,
                                    !(ci == 0 && pat == 0 && k == 0));
                    }
                }
            TC_COMMIT(mbar_o);
        }
        __syncthreads();
    }

    mbar_wait(mbar_o, po);
    TC_FENCE_AFTER();

    {
        const float inv = 1.0f / l_i;
        const int tok = b * Sn + q0 + (grow & 63);
        const int head = kvh * 4 + (grow >> 6);
        __nv_bfloat16* bh = ohi + (size_t)tok * DM + head * HD;
        __nv_bfloat16* bl = olo + (size_t)tok * DM + head * HD;
#pragma unroll
        for (int c = 0; c < 4; ++c) {
            uint32_t ov[32];
            TC_LD_X32(ov, tmO + atom * 128 + c * 32);
            TC_WAIT_LD();
#pragma unroll
            for (int g = 0; g < 4; ++g) {
                uint32_t ph[4], pl[4];
#pragma unroll
                for (int e = 0; e < 4; ++e) {
                    float v0 = __uint_as_float(ov[g*8 + e*2]) * inv;
                    float v1 = __uint_as_float(ov[g*8 + e*2 + 1]) * inv;
                    __nv_bfloat16 h0 = __float2bfloat16_rn(v0);
                    __nv_bfloat16 h1 = __float2bfloat16_rn(v1);
                    __nv_bfloat16 l0 = __float2bfloat16_rn(v0 - __bfloat162float(h0));
                    __nv_bfloat16 l1 = __float2bfloat16_rn(v1 - __bfloat162float(h1));
                    ph[e] = ((uint32_t)__bfloat16_as_ushort(h1) << 16) |
                            (uint32_t)__bfloat16_as_ushort(h0);
                    pl[e] = ((uint32_t)__bfloat16_as_ushort(l1) << 16) |
                            (uint32_t)__bfloat16_as_ushort(l0);
                }
                *(uint4*)(bh + c * 32 + g * 8) = make_uint4(ph[0], ph[1], ph[2], ph[3]);
                *(uint4*)(bl + c * 32 + g * 8) = make_uint4(pl[0], pl[1], pl[2], pl[3]);
            }
        }
    }
    __syncthreads();
    if (tid == 0) { MBAR_INVAL(mbar_s); MBAR_INVAL(mbar_o); }
    __syncthreads();
    if (wid == 0) { TC_RELINQ(); TC_DEALLOC(tmem, 512); }
#endif
}

// ---------------------------------------------------------------------------
// Pre-pass kernels
// ---------------------------------------------------------------------------
__global__ __launch_bounds__(256) void convert_split(
    const float* __restrict__ x, __nv_bfloat16* __restrict__ hi,
    __nv_bfloat16* __restrict__ lo, int n4)
{
    int i = blockIdx.x * 256 + threadIdx.x;
    if (i >= n4) return;
    float4 v = ((const float4*)x)[i];
    __nv_bfloat16 h[4], l[4];
    float vv[4] = {v.x, v.y, v.z, v.w};
#pragma unroll
    for (int j = 0; j < 4; ++j) {
        h[j] = __float2bfloat16_rn(vv[j]);
        l[j] = __float2bfloat16_rn(vv[j] - __bfloat162float(h[j]));
    }
    ((uint64_t*)hi)[i] = *(uint64_t*)h;
    ((uint64_t*)lo)[i] = *(uint64_t*)l;
}

// W[K][N] fp32 -> tile-major pre-swizzled bf16 hi/lo tiles (for bulk staging)
__global__ __launch_bounds__(256) void transpose_split_tiled(
    const float* __restrict__ W, unsigned char* __restrict__ Bt,
    int K, int N, int noff)
{
    __shared__ float tile[32][33];
    const int n0 = blockIdx.x * 32, k0 = blockIdx.y * 32;
    const int tx = threadIdx.x, ty = threadIdx.y;
#pragma unroll
    for (int i = 0; i < 32; i += 8)
        tile[ty + i][tx] = W[(size_t)(k0 + ty + i) * N + n0 + tx];
    __syncthreads();
#pragma unroll
    for (int i = 0; i < 32; i += 8) {
        float v = tile[tx][ty + i];
        __nv_bfloat16 h = __float2bfloat16_rn(v);
        __nv_bfloat16 l = __float2bfloat16_rn(v - __bfloat162float(h));
        int n = noff + n0 + ty + i;
        int k = k0 + tx;
        int nblk = n >> 8, row = n & 255, kt = k >> 5, c = k & 31;
        unsigned char* tb = Bt + ((size_t)nblk * (K >> 5) + kt) * 32768;
        *(__nv_bfloat16*)(tb + SMEM_SW128((uint32_t)(row * 128 + c * 2))) = h;
        *(__nv_bfloat16*)(tb + SMEM_SW128((uint32_t)(row * 128 + 64 + c * 2))) = l;
    }
}

__global__ __launch_bounds__(256) void v_split_t(
    const float* __restrict__ v, __nv_bfloat16* __restrict__ vth,
    __nv_bfloat16* __restrict__ vtl)
{
    __shared__ float tile[32][33];
    const int t0 = blockIdx.x * 32, d0 = blockIdx.y * 32;
    const int bkk = blockIdx.z;
    const int bb = bkk >> 3, kvh = bkk & 7;
    const int tx = threadIdx.x, ty = threadIdx.y;
#pragma unroll
    for (int i = 0; i < 32; i += 8)
        tile[ty + i][tx] = v[(size_t)(bb * Sn + t0 + ty + i) * KVD + kvh * HD + d0 + tx];
    __syncthreads();
#pragma unroll
    for (int i = 0; i < 32; i += 8) {
        float x = tile[tx][ty + i];
        __nv_bfloat16 h = __float2bfloat16_rn(x);
        size_t idx = (size_t)bkk * HD * Sn + (size_t)(d0 + ty + i) * Sn + t0 + tx;
        vth[idx] = h;
        vtl[idx] = __float2bfloat16_rn(x - __bfloat162float(h));
    }
}

__global__ __launch_bounds__(256) void rope_split(
    const float* __restrict__ q, const float* __restrict__ k,
    __nv_bfloat16* __restrict__ qsh, __nv_bfloat16* __restrict__ qsl,
    __nv_bfloat16* __restrict__ ksh, __nv_bfloat16* __restrict__ ksl,
    const int* __restrict__ pos_ids)
{
    const int tok = blockIdx.x;
    __shared__ float cs[64], sn[64];
    const int tid = threadIdx.x;
    const float pos = (float)pos_ids[tok];
    const float SCALE = 0.08838834764831845f;
    if (tid < 64) {
        float inv = powf(1.0e6f, -((float)tid) / 64.0f);
        sincosf(pos * inv, &sn[tid], &cs[tid]);
    }
    __syncthreads();
    for (int p = tid; p < (Hq + KVH) * 64; p += 256) {
        int head = p >> 6, i = p & 63;
        float c = cs[i], s = sn[i];
        if (head < Hq) {
            size_t base = (size_t)tok * DM + head * HD;
            float x1 = q[base + i], x2 = q[base + i + 64];
            float y1 = (x1 * c - x2 * s) * SCALE;
            float y2 = (x2 * c + x1 * s) * SCALE;
            __nv_bfloat16 h1 = __float2bfloat16_rn(y1);
            __nv_bfloat16 h2 = __float2bfloat16_rn(y2);
            qsh[base + i] = h1;
            qsh[base + i + 64] = h2;
            qsl[base + i] = __float2bfloat16_rn(y1 - __bfloat162float(h1));
            qsl[base + i + 64] = __float2bfloat16_rn(y2 - __bfloat162float(h2));
        } else {
            size_t base = (size_t)tok * KVD + (head - Hq) * HD;
            float x1 = k[base + i], x2 = k[base + i + 64];
            float y1 = x1 * c - x2 * s;
            float y2 = x2 * c + x1 * s;
            __nv_bfloat16 h1 = __float2bfloat16_rn(y1);
            __nv_bfloat16 h2 = __float2bfloat16_rn(y2);
            ksh[base + i] = h1;
            ksh[base + i + 64] = h2;
            ksl[base + i] = __float2bfloat16_rn(y1 - __bfloat162float(h1));
            ksl[base + i + 64] = __float2bfloat16_rn(y2 - __bfloat162float(h2));
        }
    }
}

// ---------------------------------------------------------------------------
extern "C" void kernel_launch(void* const* d_in, const int* in_sizes, int n_in,
                              void* d_out, int out_size)
{
    const float* hidden = (const float*)d_in[0];
    const float* Wq = (const float*)d_in[1];
    const float* Wk = (const float*)d_in[2];
    const float* Wv = (const float*)d_in[3];
    const float* Wo = (const float*)d_in[4];
    const int* pos_ids = (const int*)d_in[8];
    float* out = (float*)d_out;

    float *qp, *kp, *vp;
    __nv_bfloat16 *ahi, *alo, *qsh, *qsl, *ksh, *ksl, *vth, *vtl, *oh, *ol;
    unsigned char *wqt, *wkvt, *wot;
    cudaGetSymbolAddress((void**)&qp, g_q);
    cudaGetSymbolAddress((void**)&kp, g_k);
    cudaGetSymbolAddress((void**)&vp, g_v);
    cudaGetSymbolAddress((void**)&ahi, g_a_hi);
    cudaGetSymbolAddress((void**)&alo, g_a_lo);
    cudaGetSymbolAddress((void**)&wqt, g_wq_t);
    cudaGetSymbolAddress((void**)&wkvt, g_wkv_t);
    cudaGetSymbolAddress((void**)&wot, g_wo_t);
    cudaGetSymbolAddress((void**)&qsh, g_qs_hi);
    cudaGetSymbolAddress((void**)&qsl, g_qs_lo);
    cudaGetSymbolAddress((void**)&ksh, g_ks_hi);
    cudaGetSymbolAddress((void**)&ksl, g_ks_lo);
    cudaGetSymbolAddress((void**)&vth, g_vt_hi);
    cudaGetSymbolAddress((void**)&vtl, g_vt_lo);
    cudaGetSymbolAddress((void**)&oh, g_o_hi);
    cudaGetSymbolAddress((void**)&ol, g_o_lo);

    cudaFuncSetAttribute(tc_gemm2, cudaFuncAttributeMaxDynamicSharedMemorySize, GS_DYN);
    cudaFuncSetAttribute(tc_attn, cudaFuncAttributeMaxDynamicSharedMemorySize, AT_DYN);

    // pre-pass
    convert_split<<<(NTOK * DM / 4) / 256, 256>>>(hidden, ahi, alo, NTOK * DM / 4);
    transpose_split_tiled<<<dim3(DM / 32, DM / 32), dim3(32, 8)>>>(Wq, wqt, DM, DM, 0);
    transpose_split_tiled<<<dim3(KVD / 32, DM / 32), dim3(32, 8)>>>(Wk, wkvt, DM, KVD, 0);
    transpose_split_tiled<<<dim3(KVD / 32, DM / 32), dim3(32, 8)>>>(Wv, wkvt, DM, KVD, KVD);
    transpose_split_tiled<<<dim3(DM / 32, DM / 32), dim3(32, 8)>>>(Wo, wot, DM, DM, 0);

    // projections (cluster-2 multicast on weights)
    tc_gemm2<<<dim3(DM / 256, NTOK / 256), 256, GS_DYN>>>(
        ahi, alo, wqt, qp, qp, DM, DM, NTOK, DM, DM);
    tc_gemm2<<<dim3(2 * KVD / 256, NTOK / 256), 256, GS_DYN>>>(
        ahi, alo, wkvt, kp, vp, KVD, KVD, NTOK, 2 * KVD, DM);

    // rope + attention operand prep
    rope_split<<<NTOK, 256>>>(qp, kp, qsh, qsl, ksh, ksl, pos_ids);
    v_split_t<<<dim3(Sn / 32, HD / 32, Bn * KVH), dim3(32, 8)>>>(vp, vth, vtl);

    // attention
    tc_attn<<<dim3(Sn / 64, KVH, Bn), 256, AT_DYN>>>(
        qsh, qsl, ksh, ksl, vth, vtl, oh, ol);

    // output projection
    tc_gemm2<<<dim3(DM / 256, NTOK / 256), 256, GS_DYN>>>(
        oh, ol, wot, out, out, DM, DM, NTOK, DM, DM);
}

// round 11
// speedup vs baseline: 1.0426x; 1.0426x over previous
#include <cuda_runtime.h>
#include <cuda_bf16.h>
#include <math.h>
#include <stdint.h>

#define Hq 32
#define KVH 8
#define HD 128
#define Bn 4
#define Sn 1024
#define DM 4096
#define KVD 1024
#define NTOK (Bn*Sn)
#define WINDOW 512
#define NQKV (DM + 2*KVD)   // 6144

#if defined(__CUDA_ARCH_FEAT_SM103_ALL) || defined(__CUDA_ARCH_FEAT_SM100_ALL)
#define TC_FEAT 1
#else
#define TC_FEAT 0
#endif

// Scratch
__device__ float g_v[NTOK * KVD];
__device__ float g_rope[NTOK * 128];               // [tok][cos64|sin64]
__device__ __nv_bfloat16 g_a_hi[NTOK * DM];
__device__ __nv_bfloat16 g_a_lo[NTOK * DM];
__device__ __nv_bfloat16 g_wqkv_hi[NQKV * DM];     // rows: Wq^T 0-4095, Wk^T 4096-5119, Wv^T 5120-6143
__device__ __nv_bfloat16 g_wqkv_lo[NQKV * DM];
__device__ __nv_bfloat16 g_wo_hi[DM * DM];
__device__ __nv_bfloat16 g_wo_lo[DM * DM];
__device__ __nv_bfloat16 g_qs_hi[NTOK * DM];
__device__ __nv_bfloat16 g_qs_lo[NTOK * DM];
__device__ __nv_bfloat16 g_ks_hi[NTOK * KVD];
__device__ __nv_bfloat16 g_ks_lo[NTOK * KVD];
__device__ __nv_bfloat16 g_vt_hi[NTOK * KVD];
__device__ __nv_bfloat16 g_vt_lo[NTOK * KVD];
__device__ __nv_bfloat16 g_o_hi[NTOK * DM];
__device__ __nv_bfloat16 g_o_lo[NTOK * DM];

__device__ __forceinline__ uint32_t smem_u32(const void* p) {
    uint32_t a;
    asm("{ .reg .u64 t; cvta.to.shared.u64 t, %1; cvt.u32.u64 %0, t; }"
        : "=r"(a) : "l"(p));
    return a;
}
__device__ __forceinline__ uint32_t elect_one() {
    uint32_t pred;
    asm volatile("{\n .reg .pred p;\n elect.sync _|p, 0xFFFFFFFF;\n"
                 " selp.b32 %0, 1, 0, p;\n}" : "=r"(pred));
    return pred;
}
#define SMEM_SW128(off) ((off) ^ (((off) >> 3) & 0x70))
static constexpr uint64_t DESC_BASE_SW128 =
    (uint64_t(2) << 61) | (uint64_t(1) << 46) | (uint64_t(64) << 32) |
    (uint64_t(1) << 16);
__device__ __forceinline__ uint64_t make_desc(uint32_t addr) {
    return DESC_BASE_SW128 | ((uint64_t)(addr >> 4) & 0x3FFF);
}
#define MBAR_INIT(a, n) \
    asm volatile("mbarrier.init.shared.b64 [%0], %1;" :: "r"(a), "r"(n) : "memory")
#define MBAR_INVAL(a) \
    asm volatile("mbarrier.inval.shared.b64 [%0];" :: "r"(a) : "memory")
__device__ __forceinline__ void mbar_wait(uint32_t mbar, uint32_t parity) {
    uint32_t done;
    asm volatile("{\n\t.reg .pred p;\n\t"
        "mbarrier.try_wait.parity.acquire.cta.shared::cta.b64 p, [%1], %2;\n\t"
        "selp.b32 %0, 1, 0, p;\n\t}" : "=r"(done) : "r"(mbar), "r"(parity) : "memory");
    while (!done) {
        asm volatile("{\n\t.reg .pred p;\n\t"
            "mbarrier.try_wait.parity.acquire.cta.shared::cta.b64 p, [%1], %2, 0x989680;\n\t"
            "selp.b32 %0, 1, 0, p;\n\t}" : "=r"(done) : "r"(mbar), "r"(parity) : "memory");
    }
}
#define CP_ASYNC16(dst, src) \
    asm volatile("cp.async.cg.shared.global [%0], [%1], 16;" :: "r"(dst), "l"(src))
#define CP_COMMIT() asm volatile("cp.async.commit_group;" ::: "memory")
#define CP_WAIT0()  asm volatile("cp.async.wait_group 0;" ::: "memory")
#define CP_WAIT1()  asm volatile("cp.async.wait_group 1;" ::: "memory")

#if TC_FEAT
__device__ __forceinline__ void mma_bf16_ss(
    uint32_t d_tmem, uint64_t a_desc, uint64_t b_desc, uint32_t idesc, bool acc)
{
    uint32_t en = acc ? 1u : 0u;
    asm volatile(
        "{\n\t.reg .pred p;\n\tsetp.ne.u32 p, %4, 0;\n\t"
        "tcgen05.mma.cta_group::1.kind::f16 [%0], %1, %2, %3, {%5,%5,%5,%5}, p;\n\t}"
        :: "r"(d_tmem), "l"(a_desc), "l"(b_desc), "r"(idesc), "r"(en), "r"(0u)
        : "memory");
}
#define TC_ALLOC(a, n) \
    asm volatile("tcgen05.alloc.cta_group::1.sync.aligned.shared::cta.b32 [%0], %1;" \
                 :: "r"(a), "r"((uint32_t)(n)) : "memory")
#define TC_DEALLOC(t, n) \
    asm volatile("tcgen05.dealloc.cta_group::1.sync.aligned.b32 %0, %1;" \
                 :: "r"(t), "r"((uint32_t)(n)))
#define TC_RELINQ() \
    asm volatile("tcgen05.relinquish_alloc_permit.cta_group::1.sync.aligned;")
#define TC_COMMIT(m) \
    asm volatile("tcgen05.commit.cta_group::1.mbarrier::arrive::one.shared::cluster.b64 [%0];" \
                 :: "r"(m) : "memory")
#define TC_FENCE_AFTER() asm volatile("tcgen05.fence::after_thread_sync;" ::: "memory")
#define FENCE_ASYNC_SHARED() asm volatile("fence.proxy.async.shared::cta;" ::: "memory")
#define TC_LD_X32(r, addr) \
    asm volatile("tcgen05.ld.sync.aligned.32x32b.x32.b32 " \
        "{%0,%1,%2,%3,%4,%5,%6,%7,%8,%9,%10,%11,%12,%13,%14,%15," \
        "%16,%17,%18,%19,%20,%21,%22,%23,%24,%25,%26,%27,%28,%29,%30,%31}, [%32];" \
        : "=r"((r)[0]), "=r"((r)[1]), "=r"((r)[2]), "=r"((r)[3]), \
          "=r"((r)[4]), "=r"((r)[5]), "=r"((r)[6]), "=r"((r)[7]), \
          "=r"((r)[8]), "=r"((r)[9]), "=r"((r)[10]), "=r"((r)[11]), \
          "=r"((r)[12]), "=r"((r)[13]), "=r"((r)[14]), "=r"((r)[15]), \
          "=r"((r)[16]), "=r"((r)[17]), "=r"((r)[18]), "=r"((r)[19]), \
          "=r"((r)[20]), "=r"((r)[21]), "=r"((r)[22]), "=r"((r)[23]), \
          "=r"((r)[24]), "=r"((r)[25]), "=r"((r)[26]), "=r"((r)[27]), \
          "=r"((r)[28]), "=r"((r)[29]), "=r"((r)[30]), "=r"((r)[31]) \
        : "r"(addr))
#define TC_WAIT_LD() asm volatile("tcgen05.wait::ld.sync.aligned;" ::: "memory")

// bf16 hi/lo split + pack helpers
__device__ __forceinline__ void split2(float a, float b, uint32_t& hw, uint32_t& lw) {
    __nv_bfloat16 ha = __float2bfloat16_rn(a);
    __nv_bfloat16 hb = __float2bfloat16_rn(b);
    __nv_bfloat16 la = __float2bfloat16_rn(a - __bfloat162float(ha));
    __nv_bfloat16 lb = __float2bfloat16_rn(b - __bfloat162float(hb));
    hw = ((uint32_t)__bfloat16_as_ushort(hb) << 16) | (uint32_t)__bfloat16_as_ushort(ha);
    lw = ((uint32_t)__bfloat16_as_ushort(lb) << 16) | (uint32_t)__bfloat16_as_ushort(la);
}
#endif

// ---------------------------------------------------------------------------
// Shared GEMM mainloop config (R8-proven): 256x256 tile, K-tile 32, 3 stages.
// ---------------------------------------------------------------------------
#define TCG_OFF_B 32768
#define G_STAGE   65536
#define G_MBAR    (3 * G_STAGE)
#define G_TPTR    (3 * G_STAGE + 32)
#define G_DYN     (3 * G_STAGE + 64 + 1024)
#define G_IDESC   ((1u<<4)|(1u<<7)|(1u<<10)|(32u<<17)|(8u<<24))   // N=256

#if TC_FEAT
// Mainloop body used by both GEMM kernels. Leaves accumulators in TMEM.
#define GEMM_MAINLOOP(Ahi, Alo, Bhi, Blo, Kdim, m0v, n0v)                        \
    const int T = (Kdim) >> 5;                                                   \
    auto stage = [&](int t) {                                                    \
        const uint32_t sbase = smb_u + (t % 3) * G_STAGE;                        \
        const int k0 = t * 32;                                                   \
        _Pragma("unroll")                                                        \
        for (int r = 0; r < 8; ++r) {                                            \
            int i = tid + r * 256;                                               \
            int row = i >> 3, c = i & 7;                                         \
            uint32_t dst = sbase + SMEM_SW128((uint32_t)(row * 128 + c * 16));   \
            const __nv_bfloat16* src = ((c & 4) ? (Alo) : (Ahi))                 \
                + (size_t)((m0v) + row) * (Kdim) + k0 + (c & 3) * 8;             \
            CP_ASYNC16(dst, src);                                                \
        }                                                                        \
        _Pragma("unroll")                                                        \
        for (int r = 0; r < 8; ++r) {                                            \
            int i = tid + r * 256;                                               \
            int row = i >> 3, c = i & 7;                                         \
            uint32_t dst = sbase + TCG_OFF_B +                                   \
                           SMEM_SW128((uint32_t)(row * 128 + c * 16));           \
            const __nv_bfloat16* src = ((c & 4) ? (Blo) : (Bhi))                 \
                + (size_t)((n0v) + row) * (Kdim) + k0 + (c & 3) * 8;             \
            CP_ASYNC16(dst, src);                                                \
        }                                                                        \
        CP_COMMIT();                                                             \
    };                                                                           \
    stage(0); stage(1);                                                          \
    for (int t = 0; t < T; ++t) {                                                \
        if (t < T - 1) { CP_WAIT1(); } else { CP_WAIT0(); }                      \
        FENCE_ASYNC_SHARED();                                                    \
        __syncthreads();                                                         \
        if (wid == 0 && elect_one()) {                                           \
            const uint32_t sbase = smb_u + (t % 3) * G_STAGE;                    \
            uint64_t da = make_desc(sbase);                                      \
            uint64_t db = make_desc(sbase + TCG_OFF_B);                          \
            _Pragma("unroll")                                                    \
            for (int k = 0; k < 2; ++k)                                          \
                _Pragma("unroll")                                                \
                for (int m = 0; m < 2; ++m) {                                    \
                    uint32_t d = tmem + m * 256;                                 \
                    uint64_t ao = (uint64_t)(m * 1024);                          \
                    bool first = (t == 0) && (k == 0);                           \
                    mma_bf16_ss(d, da + ao + k * 2,     db + k * 2,     G_IDESC, !first); \
                    mma_bf16_ss(d, da + ao + k * 2,     db + 4 + k * 2, G_IDESC, true);   \
                    mma_bf16_ss(d, da + ao + 4 + k * 2, db + k * 2,     G_IDESC, true);   \
                }                                                                \
            TC_COMMIT(smb_u + G_MBAR + 8 * (t % 3));                             \
        }                                                                        \
        if (t + 2 < T) {                                                         \
            if (t >= 1)                                                          \
                mbar_wait(smb_u + G_MBAR + 8 * ((t + 2) % 3),                    \
                          (uint32_t)(((t - 1) / 3) & 1));                        \
            stage(t + 2);                                                        \
        }                                                                        \
    }                                                                            \
    _Pragma("unroll")                                                            \
    for (int i = 0; i < 3; ++i) {                                                \
        int cnt = (T + 2 - i) / 3;                                               \
        if (cnt > 0) mbar_wait(smb_u + G_MBAR + 8 * i, (uint32_t)((cnt - 1) & 1)); \
    }                                                                            \
    TC_FENCE_AFTER();

#define GEMM_PROLOG()                                                            \
    extern __shared__ char dsm[];                                                \
    char* smb = (char*)(((uintptr_t)dsm + 1023) & ~(uintptr_t)1023);             \
    const uint32_t smb_u = smem_u32(smb);                                        \
    const int tid = threadIdx.x;                                                 \
    const int wid = tid >> 5;                                                    \
    const int lane = tid & 31;                                                   \
    if (wid == 0) TC_ALLOC(smb_u + G_TPTR, 512);                                 \
    if (tid == 0) {                                                              \
        MBAR_INIT(smb_u + G_MBAR + 0, 1);                                        \
        MBAR_INIT(smb_u + G_MBAR + 8, 1);                                        \
        MBAR_INIT(smb_u + G_MBAR + 16, 1);                                       \
    }                                                                            \
    __syncthreads();                                                             \
    uint32_t tmem;                                                               \
    asm volatile("ld.shared.b32 %0, [%1];" : "=r"(tmem) : "r"(smb_u + G_TPTR));

#define GEMM_EPILOG_CLEANUP()                                                    \
    __syncthreads();                                                             \
    if (tid == 0) {                                                              \
        MBAR_INVAL(smb_u + G_MBAR + 0);                                          \
        MBAR_INVAL(smb_u + G_MBAR + 8);                                          \
        MBAR_INVAL(smb_u + G_MBAR + 16);                                         \
    }                                                                            \
    __syncthreads();                                                             \
    if (wid == 0) { TC_RELINQ(); TC_DEALLOC(tmem, 512); }
#endif // TC_FEAT

// ---------------------------------------------------------------------------
// Plain GEMM (Wo projection): fp32 epilogue.
// ---------------------------------------------------------------------------
__global__ __launch_bounds__(256, 1) void tc_gemm_p(
    const __nv_bfloat16* __restrict__ Ahi, const __nv_bfloat16* __restrict__ Alo,
    const __nv_bfloat16* __restrict__ Bhi, const __nv_bfloat16* __restrict__ Blo,
    float* __restrict__ C, int ldc, int K)
{
#if TC_FEAT
    GEMM_PROLOG();
    const int m0 = blockIdx.y * 256;
    const int n0 = blockIdx.x * 256;
    GEMM_MAINLOOP(Ahi, Alo, Bhi, Blo, K, m0, n0);
    {
        const int half = wid >> 2;
        const int mloc = (wid & 3) * 32 + lane;
        float* crow = C + (size_t)(m0 + half * 128 + mloc) * ldc + n0;
        uint32_t regs[32];
#pragma unroll
        for (int c = 0; c < 8; ++c) {
            TC_LD_X32(regs, tmem + half * 256 + c * 32);
            TC_WAIT_LD();
#pragma unroll
            for (int i = 0; i < 8; ++i)
                *(float4*)(crow + c * 32 + 4 * i) = make_float4(
                    __uint_as_float(regs[4*i]), __uint_as_float(regs[4*i+1]),
                    __uint_as_float(regs[4*i+2]), __uint_as_float(regs[4*i+3]));
        }
    }
    GEMM_EPILOG_CLEANUP();
#endif
}

// ---------------------------------------------------------------------------
// Fused QKV GEMM: N=6144. Epilogue:
//   n0 <  4096 : Q -> rope+scale -> qs hi/lo splits
//   n0 <  5120 : K -> rope       -> ks hi/lo splits
//   else       : V -> fp32 g_v (for v_split_t)
// ---------------------------------------------------------------------------
#define SMAX_SCALE 0.08838834764831845f

__global__ __launch_bounds__(256, 1) void tc_gemm_qkv(
    const __nv_bfloat16* __restrict__ Ahi, const __nv_bfloat16* __restrict__ Alo,
    const __nv_bfloat16* __restrict__ Bhi, const __nv_bfloat16* __restrict__ Blo,
    __nv_bfloat16* __restrict__ qsh, __nv_bfloat16* __restrict__ qsl,
    __nv_bfloat16* __restrict__ ksh, __nv_bfloat16* __restrict__ ksl,
    float* __restrict__ vf, const float* __restrict__ rope, int K)
{
#if TC_FEAT
    GEMM_PROLOG();
    const int m0 = blockIdx.y * 256;
    const int n0 = blockIdx.x * 256;
    GEMM_MAINLOOP(Ahi, Alo, Bhi, Blo, K, m0, n0);
    {
        const int half = wid >> 2;
        const int mloc = (wid & 3) * 32 + lane;
        const int tok = m0 + half * 128 + mloc;
        if (n0 >= DM + KVD) {                        // V: plain fp32
            float* crow = vf + (size_t)tok * KVD + (n0 - DM - KVD);
            uint32_t regs[32];
#pragma unroll
            for (int c = 0; c < 8; ++c) {
                TC_LD_X32(regs, tmem + half * 256 + c * 32);
                TC_WAIT_LD();
#pragma unroll
                for (int i = 0; i < 8; ++i)
                    *(float4*)(crow + c * 32 + 4 * i) = make_float4(
                        __uint_as_float(regs[4*i]), __uint_as_float(regs[4*i+1]),
                        __uint_as_float(regs[4*i+2]), __uint_as_float(regs[4*i+3]));
            }
        } else {                                     // Q or K: rope + split
            const bool isQ = (n0 < DM);
            __nv_bfloat16* dh = isQ ? qsh : ksh;
            __nv_bfloat16* dl = isQ ? qsl : ksl;
            const size_t boff = isQ ? ((size_t)tok * DM + n0)
                                    : ((size_t)tok * KVD + (n0 - DM));
            const float scl = isQ ? SMAX_SCALE : 1.0f;
            const float* rt = rope + (size_t)tok * 128;
#pragma unroll
            for (int pr = 0; pr < 4; ++pr) {
                const int ca = (pr & 1) + (pr >> 1) * 4;   // 0,1,4,5
                const int cb = ca + 2;
                uint32_t va[32], vb[32];
                TC_LD_X32(va, tmem + half * 256 + ca * 32);
                TC_LD_X32(vb, tmem + half * 256 + cb * 32);
                TC_WAIT_LD();
                const int d0 = (ca & 3) * 32;
#pragma unroll
                for (int g = 0; g < 4; ++g) {
                    uint32_t w1h[4], w1l[4], w2h[4], w2l[4];
#pragma unroll
                    for (int e = 0; e < 4; ++e) {
                        int i = g * 8 + e * 2;
                        float c0 = rt[d0 + i],     s0 = rt[64 + d0 + i];
                        float c1 = rt[d0 + i + 1], s1 = rt[64 + d0 + i + 1];
                        float x1a = __uint_as_float(va[i]) * scl;
                        float x2a = __uint_as_float(vb[i]) * scl;
                        float x1b = __uint_as_float(va[i + 1]) * scl;
                        float x2b = __uint_as_float(vb[i + 1]) * scl;
                        float y1a = x1a * c0 - x2a * s0;
                        float y2a = x2a * c0 + x1a * s0;
                        float y1b = x1b * c1 - x2b * s1;
                        float y2b = x2b * c1 + x1b * s1;
                        split2(y1a, y1b, w1h[e], w1l[e]);
                        split2(y2a, y2b, w2h[e], w2l[e]);
                    }
                    *(uint4*)(dh + boff + ca * 32 + g * 8) =
                        make_uint4(w1h[0], w1h[1], w1h[2], w1h[3]);
                    *(uint4*)(dl + boff + ca * 32 + g * 8) =
                        make_uint4(w1l[0], w1l[1], w1l[2], w1l[3]);
                    *(uint4*)(dh + boff + cb * 32 + g * 8) =
                        make_uint4(w2h[0], w2h[1], w2h[2], w2h[3]);
                    *(uint4*)(dl + boff + cb * 32 + g * 8) =
                        make_uint4(w2l[0], w2l[1], w2l[2], w2l[3]);
                }
            }
        }
    }
    GEMM_EPILOG_CLEANUP();
#endif
}

// ---------------------------------------------------------------------------
// tcgen05 attention (unchanged from R8).
// ---------------------------------------------------------------------------
#define AT_Q     0
#define AT_KP    131072
#define AT_V     196608
#define AT_MBAR  229376
#define AT_TPTR  229408
#define AT_DYN   (229440 + 1024)
#define IDESC_S  ((1u<<4)|(1u<<7)|(1u<<10)|(8u<<17)|(8u<<24))
#define IDESC_O  ((1u<<4)|(1u<<7)|(1u<<10)|(16u<<17)|(8u<<24))
#define SMAX_C   12.0f

__global__ __launch_bounds__(256, 1) void tc_attn(
    const __nv_bfloat16* __restrict__ qsh, const __nv_bfloat16* __restrict__ qsl,
    const __nv_bfloat16* __restrict__ ksh, const __nv_bfloat16* __restrict__ ksl,
    const __nv_bfloat16* __restrict__ vth, const __nv_bfloat16* __restrict__ vtl,
    __nv_bfloat16* __restrict__ ohi, __nv_bfloat16* __restrict__ olo)
{
#if TC_FEAT
    extern __shared__ char dsm[];
    char* smb = (char*)(((uintptr_t)dsm + 1023) & ~(uintptr_t)1023);
    const uint32_t smb_u = smem_u32(smb);
    const uint32_t mbar_s = smb_u + AT_MBAR;
    const uint32_t mbar_o = smb_u + AT_MBAR + 8;
    const int tid = threadIdx.x;
    const int wid = tid >> 5;
    const int q0 = (int)(gridDim.x - 1 - blockIdx.x) * 64;
    const int kvh = blockIdx.y;
    const int b = blockIdx.z;
    const int bk = b * KVH + kvh;

    if (wid == 0) TC_ALLOC(smb_u + AT_TPTR, 512);
    if (tid == 0) { MBAR_INIT(mbar_s, 1); MBAR_INIT(mbar_o, 1); }
    __syncthreads();
    uint32_t tmem;
    asm volatile("ld.shared.b32 %0, [%1];" : "=r"(tmem) : "r"(smb_u + AT_TPTR));
    const uint32_t tmS = tmem;
    const uint32_t tmO = tmem + 128;

#pragma unroll
    for (int r = 0; r < 32; ++r) {
        int u = tid + r * 256;
        int row = u >> 5, cc = u & 31;
        int s = cc >> 4, hh = (cc >> 3) & 1, c = cc & 7;
        uint32_t byte = (uint32_t)(((row >> 3) + (s * 2 + hh) * 32) * 1024 +
                                   (row & 7) * 128 + c * 16);
        int tok = b * Sn + q0 + (row & 63);
        int head = kvh * 4 + (row >> 6);
        const __nv_bfloat16* src = (s ? qsl : qsh)
            + (size_t)tok * DM + head * HD + hh * 64 + c * 8;
        CP_ASYNC16(smb_u + AT_Q + SMEM_SW128(byte), src);
    }
    CP_COMMIT();

    const int kc0 = (q0 >= WINDOW) ? (q0 - WINDOW) : 0;
    const int nch = (q0 - kc0) / 64 + 1;
    float l_i = 0.f;
    uint32_t ps = 0, po = 0;
    const int atom = wid >> 2;
    const int grow = tid;
    const int qi = q0 + (grow & 63);

    for (int ci = 0; ci < nch; ++ci) {
        const int kc = kc0 + ci * 64;
        if (ci > 0) { mbar_wait(mbar_o, po); po ^= 1; }

#pragma unroll
        for (int r = 0; r < 8; ++r) {
            int u = tid + r * 256;
            int key = u >> 5, cc = u & 31;
            int s = cc >> 4, hh = (cc >> 3) & 1, c = cc & 7;
            uint32_t byte = (uint32_t)(((key >> 3) + (s * 2 + hh) * 8) * 1024 +
                                       (key & 7) * 128 + c * 16);
            const __nv_bfloat16* src = (s ? ksl : ksh)
                + (size_t)(b * Sn + kc + key) * KVD + kvh * HD + hh * 64 + c * 8;
            CP_ASYNC16(smb_u + AT_KP + SMEM_SW128(byte), src);
        }
        CP_COMMIT();
#pragma unroll
        for (int r = 0; r < 8; ++r) {
            int u = tid + r * 256;
            int d = u >> 4, cc = u & 15;
            int s = cc >> 3, c = cc & 7;
            uint32_t byte = (uint32_t)(((d >> 3) + s * 16) * 1024 +
                                       (d & 7) * 128 + c * 16);
            const __nv_bfloat16* src = (s ? vtl : vth)
                + (size_t)bk * HD * Sn + (size_t)d * Sn + kc + c * 8;
            CP_ASYNC16(smb_u + AT_V + SMEM_SW128(byte), src);
        }
        CP_COMMIT();
        CP_WAIT1();
        FENCE_ASYNC_SHARED();
        __syncthreads();

        if (wid == 0 && elect_one()) {
            uint64_t dq = make_desc(smb_u + AT_Q);
            uint64_t dk = make_desc(smb_u + AT_KP);
#pragma unroll
            for (int m = 0; m < 2; ++m)
#pragma unroll
                for (int pat = 0; pat < 3; ++pat) {
                    int sa = (pat == 2), sb = (pat == 1);
#pragma unroll
                    for (int k = 0; k < 8; ++k) {
                        uint64_t qo = (uint64_t)(m * 1024 +
                                      (sa * 2 + (k >> 2)) * 2048 + (k & 3) * 2);
                        uint64_t ko = (uint64_t)((sb * 2 + (k >> 2)) * 512 + (k & 3) * 2);
                        mma_bf16_ss(tmS + m * 64, dq + qo, dk + ko, IDESC_S,
                                    !(pat == 0 && k == 0));
                    }
                }
            TC_COMMIT(mbar_s);
        }

        mbar_wait(mbar_s, ps);
        ps ^= 1;
        TC_FENCE_AFTER();
        uint32_t su[64];
        TC_LD_X32(su, tmS + atom * 64);
        TC_LD_X32(su + 32, tmS + atom * 64 + 32);
        TC_WAIT_LD();
        float l_add = 0.f;
#pragma unroll
        for (int c16 = 0; c16 < 8; ++c16) {
            uint32_t wh[4], wl[4];
#pragma unroll
            for (int e = 0; e < 4; ++e) {
                int i0 = c16 * 8 + e * 2;
                int j0 = kc + i0;
                float s0 = __uint_as_float(su[i0]);
                float s1 = __uint_as_float(su[i0 + 1]);
                float p0 = ((j0 <= qi) && (j0 > qi - WINDOW)) ? __expf(s0 - SMAX_C) : 0.f;
                float p1 = ((j0+1 <= qi) && (j0+1 > qi - WINDOW)) ? __expf(s1 - SMAX_C) : 0.f;
                l_add += p0 + p1;
                split2(p0, p1, wh[e], wl[e]);
            }
            uint32_t bh = (uint32_t)((grow >> 3) * 1024 + (grow & 7) * 128 + c16 * 16);
            uint32_t bl = bh + 32 * 1024;
            *(uint4*)(smb + AT_KP + SMEM_SW128(bh)) = make_uint4(wh[0], wh[1], wh[2], wh[3]);
            *(uint4*)(smb + AT_KP + SMEM_SW128(bl)) = make_uint4(wl[0], wl[1], wl[2], wl[3]);
        }
        l_i += l_add;
        CP_WAIT0();
        FENCE_ASYNC_SHARED();
        __syncthreads();

        if (wid == 0 && elect_one()) {
            uint64_t dp = make_desc(smb_u + AT_KP);
            uint64_t dv = make_desc(smb_u + AT_V);
#pragma unroll
            for (int m = 0; m < 2; ++m)
#pragma unroll
                for (int pat = 0; pat < 3; ++pat) {
                    int sp = (pat == 2), sv = (pat == 1);
#pragma unroll
                    for (int k = 0; k < 4; ++k) {
                        uint64_t pofs = (uint64_t)(m * 1024 + sp * 2048 + k * 2);
                        uint64_t vofs = (uint64_t)(sv * 1024 + k * 2);
                        mma_bf16_ss(tmO + m * 128, dp + pofs, dv + vofs, IDESC_O,
                                    !(ci == 0 && pat == 0 && k == 0));
                    }
                }
            TC_COMMIT(mbar_o);
        }
        __syncthreads();
    }

    mbar_wait(mbar_o, po);
    TC_FENCE_AFTER();

    {
        const float inv = 1.0f / l_i;
        const int tok = b * Sn + q0 + (grow & 63);
        const int head = kvh * 4 + (grow >> 6);
        __nv_bfloat16* bh = ohi + (size_t)tok * DM + head * HD;
        __nv_bfloat16* bl = olo + (size_t)tok * DM + head * HD;
#pragma unroll
        for (int c = 0; c < 4; ++c) {
            uint32_t ov[32];
            TC_LD_X32(ov, tmO + atom * 128 + c * 32);
            TC_WAIT_LD();
#pragma unroll
            for (int g = 0; g < 4; ++g) {
                uint32_t ph[4], pl[4];
#pragma unroll
                for (int e = 0; e < 4; ++e) {
                    float v0 = __uint_as_float(ov[g*8 + e*2]) * inv;
                    float v1 = __uint_as_float(ov[g*8 + e*2 + 1]) * inv;
                    split2(v0, v1, ph[e], pl[e]);
                }
                *(uint4*)(bh + c * 32 + g * 8) = make_uint4(ph[0], ph[1], ph[2], ph[3]);
                *(uint4*)(bl + c * 32 + g * 8) = make_uint4(pl[0], pl[1], pl[2], pl[3]);
            }
        }
    }
    __syncthreads();
    if (tid == 0) { MBAR_INVAL(mbar_s); MBAR_INVAL(mbar_o); }
    __syncthreads();
    if (wid == 0) { TC_RELINQ(); TC_DEALLOC(tmem, 512); }
#endif
}

// ---------------------------------------------------------------------------
// Pre-pass kernels
// ---------------------------------------------------------------------------
__global__ __launch_bounds__(64) void rope_table(
    float* __restrict__ rt, const int* __restrict__ pos_ids)
{
    const int tok = blockIdx.x;
    const int d = threadIdx.x;                 // 0..63
    float pos = (float)pos_ids[tok];
    float inv = powf(1.0e6f, -((float)d) / 64.0f);
    float sv, cv;
    sincosf(pos * inv, &sv, &cv);
    rt[(size_t)tok * 128 + d] = cv;
    rt[(size_t)tok * 128 + 64 + d] = sv;
}

__global__ __launch_bounds__(256) void convert_split(
    const float* __restrict__ x, __nv_bfloat16* __restrict__ hi,
    __nv_bfloat16* __restrict__ lo, int n4)
{
    int i = blockIdx.x * 256 + threadIdx.x;
    if (i >= n4) return;
    float4 v = ((const float4*)x)[i];
    __nv_bfloat16 h[4], l[4];
    float vv[4] = {v.x, v.y, v.z, v.w};
#pragma unroll
    for (int j = 0; j < 4; ++j) {
        h[j] = __float2bfloat16_rn(vv[j]);
        l[j] = __float2bfloat16_rn(vv[j] - __bfloat162float(h[j]));
    }
    ((uint64_t*)hi)[i] = *(uint64_t*)h;
    ((uint64_t*)lo)[i] = *(uint64_t*)l;
}

__global__ __launch_bounds__(256) void transpose_split(
    const float* __restrict__ W, __nv_bfloat16* __restrict__ Thi,
    __nv_bfloat16* __restrict__ Tlo, int K, int N, int noff)
{
    __shared__ float tile[32][33];
    const int n0 = blockIdx.x * 32, k0 = blockIdx.y * 32;
    const int tx = threadIdx.x, ty = threadIdx.y;
#pragma unroll
    for (int i = 0; i < 32; i += 8)
        tile[ty + i][tx] = W[(size_t)(k0 + ty + i) * N + n0 + tx];
    __syncthreads();
#pragma unroll
    for (int i = 0; i < 32; i += 8) {
        float v = tile[tx][ty + i];
        __nv_bfloat16 h = __float2bfloat16_rn(v);
        size_t idx = (size_t)(noff + n0 + ty + i) * K + k0 + tx;
        Thi[idx] = h;
        Tlo[idx] = __float2bfloat16_rn(v - __bfloat162float(h));
    }
}

__global__ __launch_bounds__(256) void v_split_t(
    const float* __restrict__ v, __nv_bfloat16* __restrict__ vth,
    __nv_bfloat16* __restrict__ vtl)
{
    __shared__ float tile[32][33];
    const int t0 = blockIdx.x * 32, d0 = blockIdx.y * 32;
    const int bkk = blockIdx.z;
    const int bb = bkk >> 3, kvh = bkk & 7;
    const int tx = threadIdx.x, ty = threadIdx.y;
#pragma unroll
    for (int i = 0; i < 32; i += 8)
        tile[ty + i][tx] = v[(size_t)(bb * Sn + t0 + ty + i) * KVD + kvh * HD + d0 + tx];
    __syncthreads();
#pragma unroll
    for (int i = 0; i < 32; i += 8) {
        float x = tile[tx][ty + i];
        __nv_bfloat16 h = __float2bfloat16_rn(x);
        size_t idx = (size_t)bkk * HD * Sn + (size_t)(d0 + ty + i) * Sn + t0 + tx;
        vth[idx] = h;
        vtl[idx] = __float2bfloat16_rn(x - __bfloat162float(h));
    }
}

// ---------------------------------------------------------------------------
extern "C" void kernel_launch(void* const* d_in, const int* in_sizes, int n_in,
                              void* d_out, int out_size)
{
    const float* hidden = (const float*)d_in[0];
    const float* Wq = (const float*)d_in[1];
    const float* Wk = (const float*)d_in[2];
    const float* Wv = (const float*)d_in[3];
    const float* Wo = (const float*)d_in[4];
    const int* pos_ids = (const int*)d_in[8];
    float* out = (float*)d_out;

    float *vp, *rt;
    __nv_bfloat16 *ahi, *alo, *wqkvh, *wqkvl, *woh, *wol;
    __nv_bfloat16 *qsh, *qsl, *ksh, *ksl, *vth, *vtl, *oh, *ol;
    cudaGetSymbolAddress((void**)&vp, g_v);
    cudaGetSymbolAddress((void**)&rt, g_rope);
    cudaGetSymbolAddress((void**)&ahi, g_a_hi);
    cudaGetSymbolAddress((void**)&alo, g_a_lo);
    cudaGetSymbolAddress((void**)&wqkvh, g_wqkv_hi);
    cudaGetSymbolAddress((void**)&wqkvl, g_wqkv_lo);
    cudaGetSymbolAddress((void**)&woh, g_wo_hi);
    cudaGetSymbolAddress((void**)&wol, g_wo_lo);
    cudaGetSymbolAddress((void**)&qsh, g_qs_hi);
    cudaGetSymbolAddress((void**)&qsl, g_qs_lo);
    cudaGetSymbolAddress((void**)&ksh, g_ks_hi);
    cudaGetSymbolAddress((void**)&ksl, g_ks_lo);
    cudaGetSymbolAddress((void**)&vth, g_vt_hi);
    cudaGetSymbolAddress((void**)&vtl, g_vt_lo);
    cudaGetSymbolAddress((void**)&oh, g_o_hi);
    cudaGetSymbolAddress((void**)&ol, g_o_lo);

    cudaFuncSetAttribute(tc_gemm_p, cudaFuncAttributeMaxDynamicSharedMemorySize, G_DYN);
    cudaFuncSetAttribute(tc_gemm_qkv, cudaFuncAttributeMaxDynamicSharedMemorySize, G_DYN);
    cudaFuncSetAttribute(tc_attn, cudaFuncAttributeMaxDynamicSharedMemorySize, AT_DYN);

    // pre-pass
    rope_table<<<NTOK, 64>>>(rt, pos_ids);
    convert_split<<<(NTOK * DM / 4) / 256, 256>>>(hidden, ahi, alo, NTOK * DM / 4);
    transpose_split<<<dim3(DM / 32, DM / 32), dim3(32, 8)>>>(Wq, wqkvh, wqkvl, DM, DM, 0);
    transpose_split<<<dim3(KVD / 32, DM / 32), dim3(32, 8)>>>(Wk, wqkvh, wqkvl, DM, KVD, DM);
    transpose_split<<<dim3(KVD / 32, DM / 32), dim3(32, 8)>>>(Wv, wqkvh, wqkvl, DM, KVD, DM + KVD);
    transpose_split<<<dim3(DM / 32, DM / 32), dim3(32, 8)>>>(Wo, woh, wol, DM, DM, 0);

    // fused QKV projection + rope + split (N=6144)
    tc_gemm_qkv<<<dim3(NQKV / 256, NTOK / 256), 256, G_DYN>>>(
        ahi, alo, wqkvh, wqkvl, qsh, qsl, ksh, ksl, vp, rt, DM);

    // V transpose+split for attention
    v_split_t<<<dim3(Sn / 32, HD / 32, Bn * KVH), dim3(32, 8)>>>(vp, vth, vtl);

    // attention (writes bf16 splits directly)
    tc_attn<<<dim3(Sn / 64, KVH, Bn), 256, AT_DYN>>>(
        qsh, qsl, ksh, ksl, vth, vtl, oh, ol);

    // output projection
    tc_gemm_p<<<dim3(DM / 256, NTOK / 256), 256, G_DYN>>>(
        oh, ol, woh, wol, out, DM, DM);
}

// round 12
// speedup vs baseline: 1.0527x; 1.0098x over previous
#include <cuda_runtime.h>
#include <cuda_bf16.h>
#include <math.h>
#include <stdint.h>

#define Hq 32
#define KVH 8
#define HD 128
#define Bn 4
#define Sn 1024
#define DM 4096
#define KVD 1024
#define NTOK (Bn*Sn)
#define WINDOW 512

#if defined(__CUDA_ARCH_FEAT_SM103_ALL) || defined(__CUDA_ARCH_FEAT_SM100_ALL)
#define TC_FEAT 1
#else
#define TC_FEAT 0
#endif

// Scratch
__device__ float g_q[NTOK * DM];
__device__ float g_k[NTOK * KVD];
__device__ float g_v[NTOK * KVD];
__device__ __nv_bfloat16 g_a_hi[NTOK * DM];
__device__ __nv_bfloat16 g_a_lo[NTOK * DM];
// tile-major pre-swizzled weights: [nblk][ktile][32KB]; row = [hi 64B | lo 64B]
__device__ __align__(128) unsigned char g_wq_t[(DM/256) * (DM/32) * 32768];
__device__ __align__(128) unsigned char g_wkv_t[(2*KVD/256) * (DM/32) * 32768];
__device__ __align__(128) unsigned char g_wo_t[(DM/256) * (DM/32) * 32768];
__device__ __nv_bfloat16 g_qs_hi[NTOK * DM];
__device__ __nv_bfloat16 g_qs_lo[NTOK * DM];
__device__ __nv_bfloat16 g_ks_hi[NTOK * KVD];
__device__ __nv_bfloat16 g_ks_lo[NTOK * KVD];
__device__ __nv_bfloat16 g_vt_hi[NTOK * KVD];
__device__ __nv_bfloat16 g_vt_lo[NTOK * KVD];
__device__ __nv_bfloat16 g_o_hi[NTOK * DM];
__device__ __nv_bfloat16 g_o_lo[NTOK * DM];

__device__ __forceinline__ uint32_t smem_u32(const void* p) {
    uint32_t a;
    asm("{ .reg .u64 t; cvta.to.shared.u64 t, %1; cvt.u32.u64 %0, t; }"
        : "=r"(a) : "l"(p));
    return a;
}
__device__ __forceinline__ uint32_t elect_one() {
    uint32_t pred;
    asm volatile("{\n .reg .pred p;\n elect.sync _|p, 0xFFFFFFFF;\n"
                 " selp.b32 %0, 1, 0, p;\n}" : "=r"(pred));
    return pred;
}
#define SMEM_SW128(off) ((off) ^ (((off) >> 3) & 0x70))
static constexpr uint64_t DESC_BASE_SW128 =
    (uint64_t(2) << 61) | (uint64_t(1) << 46) | (uint64_t(64) << 32) |
    (uint64_t(1) << 16);
__device__ __forceinline__ uint64_t make_desc(uint32_t addr) {
    return DESC_BASE_SW128 | ((uint64_t)(addr >> 4) & 0x3FFF);
}
#define MBAR_INIT(a, n) \
    asm volatile("mbarrier.init.shared.b64 [%0], %1;" :: "r"(a), "r"(n) : "memory")
#define MBAR_INVAL(a) \
    asm volatile("mbarrier.inval.shared.b64 [%0];" :: "r"(a) : "memory")
#define MBAR_EXPECT_TX(a, n) \
    asm volatile("mbarrier.arrive.expect_tx.shared.b64 _, [%0], %1;" \
                 :: "r"(a), "r"((uint32_t)(n)) : "memory")
// plain (cta-scope) 1D bulk copy global->shared
#define BULK_G2S(dst, src, bytes, mbar) \
    asm volatile("cp.async.bulk.shared::cta.global.mbarrier::complete_tx::bytes" \
                 " [%0], [%1], %2, [%3];" \
                 :: "r"(dst), "l"(src), "r"((uint32_t)(bytes)), "r"(mbar) : "memory")

__device__ __forceinline__ void mbar_wait(uint32_t mbar, uint32_t parity) {
    uint32_t done;
    asm volatile("{\n\t.reg .pred p;\n\t"
        "mbarrier.try_wait.parity.acquire.cta.shared::cta.b64 p, [%1], %2;\n\t"
        "selp.b32 %0, 1, 0, p;\n\t}" : "=r"(done) : "r"(mbar), "r"(parity) : "memory");
    while (!done) {
        asm volatile("{\n\t.reg .pred p;\n\t"
            "mbarrier.try_wait.parity.acquire.cta.shared::cta.b64 p, [%1], %2, 0x989680;\n\t"
            "selp.b32 %0, 1, 0, p;\n\t}" : "=r"(done) : "r"(mbar), "r"(parity) : "memory");
    }
}
#define CP_ASYNC16(dst, src) \
    asm volatile("cp.async.cg.shared.global [%0], [%1], 16;" :: "r"(dst), "l"(src))
#define CP_COMMIT() asm volatile("cp.async.commit_group;" ::: "memory")
#define CP_WAIT0()  asm volatile("cp.async.wait_group 0;" ::: "memory")
#define CP_WAIT1()  asm volatile("cp.async.wait_group 1;" ::: "memory")

#if TC_FEAT
__device__ __forceinline__ void mma_bf16_ss(
    uint32_t d_tmem, uint64_t a_desc, uint64_t b_desc, uint32_t idesc, bool acc)
{
    uint32_t en = acc ? 1u : 0u;
    asm volatile(
        "{\n\t.reg .pred p;\n\tsetp.ne.u32 p, %4, 0;\n\t"
        "tcgen05.mma.cta_group::1.kind::f16 [%0], %1, %2, %3, {%5,%5,%5,%5}, p;\n\t}"
        :: "r"(d_tmem), "l"(a_desc), "l"(b_desc), "r"(idesc), "r"(en), "r"(0u)
        : "memory");
}
#define TC_ALLOC(a, n) \
    asm volatile("tcgen05.alloc.cta_group::1.sync.aligned.shared::cta.b32 [%0], %1;" \
                 :: "r"(a), "r"((uint32_t)(n)) : "memory")
#define TC_DEALLOC(t, n) \
    asm volatile("tcgen05.dealloc.cta_group::1.sync.aligned.b32 %0, %1;" \
                 :: "r"(t), "r"((uint32_t)(n)))
#define TC_RELINQ() \
    asm volatile("tcgen05.relinquish_alloc_permit.cta_group::1.sync.aligned;")
#define TC_COMMIT(m) \
    asm volatile("tcgen05.commit.cta_group::1.mbarrier::arrive::one.shared::cluster.b64 [%0];" \
                 :: "r"(m) : "memory")
#define TC_FENCE_AFTER() asm volatile("tcgen05.fence::after_thread_sync;" ::: "memory")
#define FENCE_ASYNC_SHARED() asm volatile("fence.proxy.async.shared::cta;" ::: "memory")
#define TC_LD_X32(r, addr) \
    asm volatile("tcgen05.ld.sync.aligned.32x32b.x32.b32 " \
        "{%0,%1,%2,%3,%4,%5,%6,%7,%8,%9,%10,%11,%12,%13,%14,%15," \
        "%16,%17,%18,%19,%20,%21,%22,%23,%24,%25,%26,%27,%28,%29,%30,%31}, [%32];" \
        : "=r"((r)[0]), "=r"((r)[1]), "=r"((r)[2]), "=r"((r)[3]), \
          "=r"((r)[4]), "=r"((r)[5]), "=r"((r)[6]), "=r"((r)[7]), \
          "=r"((r)[8]), "=r"((r)[9]), "=r"((r)[10]), "=r"((r)[11]), \
          "=r"((r)[12]), "=r"((r)[13]), "=r"((r)[14]), "=r"((r)[15]), \
          "=r"((r)[16]), "=r"((r)[17]), "=r"((r)[18]), "=r"((r)[19]), \
          "=r"((r)[20]), "=r"((r)[21]), "=r"((r)[22]), "=r"((r)[23]), \
          "=r"((r)[24]), "=r"((r)[25]), "=r"((r)[26]), "=r"((r)[27]), \
          "=r"((r)[28]), "=r"((r)[29]), "=r"((r)[30]), "=r"((r)[31]) \
        : "r"(addr))
#define TC_WAIT_LD() asm volatile("tcgen05.wait::ld.sync.aligned;" ::: "memory")

__device__ __forceinline__ void split2(float a, float b, uint32_t& hw, uint32_t& lw) {
    __nv_bfloat16 ha = __float2bfloat16_rn(a);
    __nv_bfloat16 hb = __float2bfloat16_rn(b);
    __nv_bfloat16 la = __float2bfloat16_rn(a - __bfloat162float(ha));
    __nv_bfloat16 lb = __float2bfloat16_rn(b - __bfloat162float(hb));
    hw = ((uint32_t)__bfloat16_as_ushort(hb) << 16) | (uint32_t)__bfloat16_as_ushort(ha);
    lw = ((uint32_t)__bfloat16_as_ushort(lb) << 16) | (uint32_t)__bfloat16_as_ushort(la);
}
#endif

// ---------------------------------------------------------------------------
// tcgen05 GEMM, 256x256 tile, K-tile 32, 3 stages.
// A (activations) via cp.async (2048 ops/tile); B (weights) via ONE 32KB
// cp.async.bulk from pre-tiled, pre-swizzled gmem (issued by tid 0).
// Output routing: n0 < nsplit -> C, else C2 (fused KV).
// ---------------------------------------------------------------------------
#define G_OFF_B   32768
#define G_STAGE   65536
#define G_M_MMA   (3 * G_STAGE)          // 3 x 8B
#define G_M_FULL  (3 * G_STAGE + 32)     // 3 x 8B
#define G_TPTR    (3 * G_STAGE + 64)
#define G_DYN     (3 * G_STAGE + 96 + 1024)
#define G_IDESC   ((1u<<4)|(1u<<7)|(1u<<10)|(32u<<17)|(8u<<24))   // N=256

__global__ __launch_bounds__(256, 1) void tc_gemm(
    const __nv_bfloat16* __restrict__ Ahi, const __nv_bfloat16* __restrict__ Alo,
    const unsigned char* __restrict__ Bt,
    float* __restrict__ C, float* __restrict__ C2, int ldc, int nsplit, int K)
{
#if TC_FEAT
    extern __shared__ char dsm[];
    char* smb = (char*)(((uintptr_t)dsm + 1023) & ~(uintptr_t)1023);
    const uint32_t smb_u = smem_u32(smb);
    const int tid = threadIdx.x;
    const int wid = tid >> 5;
    const int lane = tid & 31;
    const int m0 = blockIdx.y * 256;
    const int n0 = blockIdx.x * 256;
    const int T = K >> 5;

    if (wid == 0) TC_ALLOC(smb_u + G_TPTR, 512);
    if (tid == 0) {
#pragma unroll
        for (int i = 0; i < 3; ++i) {
            MBAR_INIT(smb_u + G_M_MMA + 8 * i, 1);
            MBAR_INIT(smb_u + G_M_FULL + 8 * i, 1);
        }
        FENCE_ASYNC_SHARED();
    }
    __syncthreads();
    uint32_t tmem;
    asm volatile("ld.shared.b32 %0, [%1];" : "=r"(tmem) : "r"(smb_u + G_TPTR));

    auto stageA = [&](int t) {
        const uint32_t sbase = smb_u + (t % 3) * G_STAGE;
        const int k0 = t * 32;
#pragma unroll
        for (int r = 0; r < 8; ++r) {
            int i = tid + r * 256;
            int row = i >> 3, c = i & 7;
            uint32_t dst = sbase + SMEM_SW128((uint32_t)(row * 128 + c * 16));
            const __nv_bfloat16* src = ((c & 4) ? Alo : Ahi)
                + (size_t)(m0 + row) * K + k0 + (c & 3) * 8;
            CP_ASYNC16(dst, src);
        }
        CP_COMMIT();
    };
    auto stageB = [&](int t) {   // tid 0 only
        const int s = t % 3;
        MBAR_EXPECT_TX(smb_u + G_M_FULL + 8 * s, 32768);
        const unsigned char* src = Bt + ((size_t)blockIdx.x * T + t) * 32768;
        BULK_G2S(smb_u + s * G_STAGE + G_OFF_B, src, 32768,
                 smb_u + G_M_FULL + 8 * s);
    };

    stageA(0); stageA(1);
    if (tid == 0) { stageB(0); stageB(1); }

    for (int t = 0; t < T; ++t) {
        if (t < T - 1) { CP_WAIT1(); } else { CP_WAIT0(); }
        FENCE_ASYNC_SHARED();
        __syncthreads();

        if (wid == 0 && elect_one()) {
            mbar_wait(smb_u + G_M_FULL + 8 * (t % 3), (uint32_t)((t / 3) & 1));
            const uint32_t sbase = smb_u + (t % 3) * G_STAGE;
            uint64_t da = make_desc(sbase);
            uint64_t db = make_desc(sbase + G_OFF_B);
#pragma unroll
            for (int k = 0; k < 2; ++k)
#pragma unroll
                for (int m = 0; m < 2; ++m) {
                    uint32_t d = tmem + m * 256;
                    uint64_t ao = (uint64_t)(m * 1024);
                    bool first = (t == 0) && (k == 0);
                    mma_bf16_ss(d, da + ao + k * 2,     db + k * 2,     G_IDESC, !first);
                    mma_bf16_ss(d, da + ao + k * 2,     db + 4 + k * 2, G_IDESC, true);
                    mma_bf16_ss(d, da + ao + 4 + k * 2, db + k * 2,     G_IDESC, true);
                }
            TC_COMMIT(smb_u + G_M_MMA + 8 * (t % 3));
        }

        if (t + 2 < T) {
            if (t >= 1)
                mbar_wait(smb_u + G_M_MMA + 8 * ((t + 2) % 3),
                          (uint32_t)(((t - 1) / 3) & 1));
            stageA(t + 2);
            if (tid == 0) stageB(t + 2);
        }
    }
#pragma unroll
    for (int i = 0; i < 3; ++i) {
        int cnt = (T + 2 - i) / 3;
        if (cnt > 0) mbar_wait(smb_u + G_M_MMA + 8 * i, (uint32_t)((cnt - 1) & 1));
    }
    TC_FENCE_AFTER();

    {
        const int half = wid >> 2;
        const int mloc = (wid & 3) * 32 + lane;
        float* base;
        int col;
        if (n0 < nsplit) { base = C; col = n0; }
        else             { base = C2; col = n0 - nsplit; }
        float* crow = base + (size_t)(m0 + half * 128 + mloc) * ldc + col;
        uint32_t regs[32];
#pragma unroll
        for (int c = 0; c < 8; ++c) {
            TC_LD_X32(regs, tmem + half * 256 + c * 32);
            TC_WAIT_LD();
#pragma unroll
            for (int i = 0; i < 8; ++i)
                *(float4*)(crow + c * 32 + 4 * i) = make_float4(
                    __uint_as_float(regs[4*i]), __uint_as_float(regs[4*i+1]),
                    __uint_as_float(regs[4*i+2]), __uint_as_float(regs[4*i+3]));
        }
    }
    __syncthreads();
    if (tid == 0) {
#pragma unroll
        for (int i = 0; i < 3; ++i) {
            MBAR_INVAL(smb_u + G_M_MMA + 8 * i);
            MBAR_INVAL(smb_u + G_M_FULL + 8 * i);
        }
    }
    __syncthreads();
    if (wid == 0) { TC_RELINQ(); TC_DEALLOC(tmem, 512); }
#endif
}

// ---------------------------------------------------------------------------
// tcgen05 attention (unchanged from R8).
// ---------------------------------------------------------------------------
#define AT_Q     0
#define AT_KP    131072
#define AT_V     196608
#define AT_MBAR  229376
#define AT_TPTR  229408
#define AT_DYN   (229440 + 1024)
#define IDESC_S  ((1u<<4)|(1u<<7)|(1u<<10)|(8u<<17)|(8u<<24))
#define IDESC_O  ((1u<<4)|(1u<<7)|(1u<<10)|(16u<<17)|(8u<<24))
#define SMAX_C   12.0f

__global__ __launch_bounds__(256, 1) void tc_attn(
    const __nv_bfloat16* __restrict__ qsh, const __nv_bfloat16* __restrict__ qsl,
    const __nv_bfloat16* __restrict__ ksh, const __nv_bfloat16* __restrict__ ksl,
    const __nv_bfloat16* __restrict__ vth, const __nv_bfloat16* __restrict__ vtl,
    __nv_bfloat16* __restrict__ ohi, __nv_bfloat16* __restrict__ olo)
{
#if TC_FEAT
    extern __shared__ char dsm[];
    char* smb = (char*)(((uintptr_t)dsm + 1023) & ~(uintptr_t)1023);
    const uint32_t smb_u = smem_u32(smb);
    const uint32_t mbar_s = smb_u + AT_MBAR;
    const uint32_t mbar_o = smb_u + AT_MBAR + 8;
    const int tid = threadIdx.x;
    const int wid = tid >> 5;
    const int q0 = (int)(gridDim.x - 1 - blockIdx.x) * 64;
    const int kvh = blockIdx.y;
    const int b = blockIdx.z;
    const int bk = b * KVH + kvh;

    if (wid == 0) TC_ALLOC(smb_u + AT_TPTR, 512);
    if (tid == 0) { MBAR_INIT(mbar_s, 1); MBAR_INIT(mbar_o, 1); }
    __syncthreads();
    uint32_t tmem;
    asm volatile("ld.shared.b32 %0, [%1];" : "=r"(tmem) : "r"(smb_u + AT_TPTR));
    const uint32_t tmS = tmem;
    const uint32_t tmO = tmem + 128;

#pragma unroll
    for (int r = 0; r < 32; ++r) {
        int u = tid + r * 256;
        int row = u >> 5, cc = u & 31;
        int s = cc >> 4, hh = (cc >> 3) & 1, c = cc & 7;
        uint32_t byte = (uint32_t)(((row >> 3) + (s * 2 + hh) * 32) * 1024 +
                                   (row & 7) * 128 + c * 16);
        int tok = b * Sn + q0 + (row & 63);
        int head = kvh * 4 + (row >> 6);
        const __nv_bfloat16* src = (s ? qsl : qsh)
            + (size_t)tok * DM + head * HD + hh * 64 + c * 8;
        CP_ASYNC16(smb_u + AT_Q + SMEM_SW128(byte), src);
    }
    CP_COMMIT();

    const int kc0 = (q0 >= WINDOW) ? (q0 - WINDOW) : 0;
    const int nch = (q0 - kc0) / 64 + 1;
    float l_i = 0.f;
    uint32_t ps = 0, po = 0;
    const int atom = wid >> 2;
    const int grow = tid;
    const int qi = q0 + (grow & 63);

    for (int ci = 0; ci < nch; ++ci) {
        const int kc = kc0 + ci * 64;
        if (ci > 0) { mbar_wait(mbar_o, po); po ^= 1; }

#pragma unroll
        for (int r = 0; r < 8; ++r) {
            int u = tid + r * 256;
            int key = u >> 5, cc = u & 31;
            int s = cc >> 4, hh = (cc >> 3) & 1, c = cc & 7;
            uint32_t byte = (uint32_t)(((key >> 3) + (s * 2 + hh) * 8) * 1024 +
                                       (key & 7) * 128 + c * 16);
            const __nv_bfloat16* src = (s ? ksl : ksh)
                + (size_t)(b * Sn + kc + key) * KVD + kvh * HD + hh * 64 + c * 8;
            CP_ASYNC16(smb_u + AT_KP + SMEM_SW128(byte), src);
        }
        CP_COMMIT();
#pragma unroll
        for (int r = 0; r < 8; ++r) {
            int u = tid + r * 256;
            int d = u >> 4, cc = u & 15;
            int s = cc >> 3, c = cc & 7;
            uint32_t byte = (uint32_t)(((d >> 3) + s * 16) * 1024 +
                                       (d & 7) * 128 + c * 16);
            const __nv_bfloat16* src = (s ? vtl : vth)
                + (size_t)bk * HD * Sn + (size_t)d * Sn + kc + c * 8;
            CP_ASYNC16(smb_u + AT_V + SMEM_SW128(byte), src);
        }
        CP_COMMIT();
        CP_WAIT1();
        FENCE_ASYNC_SHARED();
        __syncthreads();

        if (wid == 0 && elect_one()) {
            uint64_t dq = make_desc(smb_u + AT_Q);
            uint64_t dk = make_desc(smb_u + AT_KP);
#pragma unroll
            for (int m = 0; m < 2; ++m)
#pragma unroll
                for (int pat = 0; pat < 3; ++pat) {
                    int sa = (pat == 2), sb = (pat == 1);
#pragma unroll
                    for (int k = 0; k < 8; ++k) {
                        uint64_t qo = (uint64_t)(m * 1024 +
                                      (sa * 2 + (k >> 2)) * 2048 + (k & 3) * 2);
                        uint64_t ko = (uint64_t)((sb * 2 + (k >> 2)) * 512 + (k & 3) * 2);
                        mma_bf16_ss(tmS + m * 64, dq + qo, dk + ko, IDESC_S,
                                    !(pat == 0 && k == 0));
                    }
                }
            TC_COMMIT(mbar_s);
        }

        mbar_wait(mbar_s, ps);
        ps ^= 1;
        TC_FENCE_AFTER();
        uint32_t su[64];
        TC_LD_X32(su, tmS + atom * 64);
        TC_LD_X32(su + 32, tmS + atom * 64 + 32);
        TC_WAIT_LD();
        float l_add = 0.f;
#pragma unroll
        for (int c16 = 0; c16 < 8; ++c16) {
            uint32_t wh[4], wl[4];
#pragma unroll
            for (int e = 0; e < 4; ++e) {
                int i0 = c16 * 8 + e * 2;
                int j0 = kc + i0;
                float s0 = __uint_as_float(su[i0]);
                float s1 = __uint_as_float(su[i0 + 1]);
                float p0 = ((j0 <= qi) && (j0 > qi - WINDOW)) ? __expf(s0 - SMAX_C) : 0.f;
                float p1 = ((j0+1 <= qi) && (j0+1 > qi - WINDOW)) ? __expf(s1 - SMAX_C) : 0.f;
                l_add += p0 + p1;
                split2(p0, p1, wh[e], wl[e]);
            }
            uint32_t bh = (uint32_t)((grow >> 3) * 1024 + (grow & 7) * 128 + c16 * 16);
            uint32_t bl = bh + 32 * 1024;
            *(uint4*)(smb + AT_KP + SMEM_SW128(bh)) = make_uint4(wh[0], wh[1], wh[2], wh[3]);
            *(uint4*)(smb + AT_KP + SMEM_SW128(bl)) = make_uint4(wl[0], wl[1], wl[2], wl[3]);
        }
        l_i += l_add;
        CP_WAIT0();
        FENCE_ASYNC_SHARED();
        __syncthreads();

        if (wid == 0 && elect_one()) {
            uint64_t dp = make_desc(smb_u + AT_KP);
            uint64_t dv = make_desc(smb_u + AT_V);
#pragma unroll
            for (int m = 0; m < 2; ++m)
#pragma unroll
                for (int pat = 0; pat < 3; ++pat) {
                    int sp = (pat == 2), sv = (pat == 1);
#pragma unroll
                    for (int k = 0; k < 4; ++k) {
                        uint64_t pofs = (uint64_t)(m * 1024 + sp * 2048 + k * 2);
                        uint64_t vofs = (uint64_t)(sv * 1024 + k * 2);
                        mma_bf16_ss(tmO + m * 128, dp + pofs, dv + vofs, IDESC_O,
                                    !(ci == 0 && pat == 0 && k == 0));
                    }
                }
            TC_COMMIT(mbar_o);
        }
        __syncthreads();
    }

    mbar_wait(mbar_o, po);
    TC_FENCE_AFTER();

    {
        const float inv = 1.0f / l_i;
        const int tok = b * Sn + q0 + (grow & 63);
        const int head = kvh * 4 + (grow >> 6);
        __nv_bfloat16* bh = ohi + (size_t)tok * DM + head * HD;
        __nv_bfloat16* bl = olo + (size_t)tok * DM + head * HD;
#pragma unroll
        for (int c = 0; c < 4; ++c) {
            uint32_t ov[32];
            TC_LD_X32(ov, tmO + atom * 128 + c * 32);
            TC_WAIT_LD();
#pragma unroll
            for (int g = 0; g < 4; ++g) {
                uint32_t ph[4], pl[4];
#pragma unroll
                for (int e = 0; e < 4; ++e) {
                    float v0 = __uint_as_float(ov[g*8 + e*2]) * inv;
                    float v1 = __uint_as_float(ov[g*8 + e*2 + 1]) * inv;
                    split2(v0, v1, ph[e], pl[e]);
                }
                *(uint4*)(bh + c * 32 + g * 8) = make_uint4(ph[0], ph[1], ph[2], ph[3]);
                *(uint4*)(bl + c * 32 + g * 8) = make_uint4(pl[0], pl[1], pl[2], pl[3]);
            }
        }
    }
    __syncthreads();
    if (tid == 0) { MBAR_INVAL(mbar_s); MBAR_INVAL(mbar_o); }
    __syncthreads();
    if (wid == 0) { TC_RELINQ(); TC_DEALLOC(tmem, 512); }
#endif
}

// ---------------------------------------------------------------------------
// Pre-pass kernels
// ---------------------------------------------------------------------------
__global__ __launch_bounds__(256) void convert_split(
    const float* __restrict__ x, __nv_bfloat16* __restrict__ hi,
    __nv_bfloat16* __restrict__ lo, int n4)
{
    int i = blockIdx.x * 256 + threadIdx.x;
    if (i >= n4) return;
    float4 v = ((const float4*)x)[i];
    __nv_bfloat16 h[4], l[4];
    float vv[4] = {v.x, v.y, v.z, v.w};
#pragma unroll
    for (int j = 0; j < 4; ++j) {
        h[j] = __float2bfloat16_rn(vv[j]);
        l[j] = __float2bfloat16_rn(vv[j] - __bfloat162float(h[j]));
    }
    ((uint64_t*)hi)[i] = *(uint64_t*)h;
    ((uint64_t*)lo)[i] = *(uint64_t*)l;
}

// W[K][N] fp32 -> tile-major pre-swizzled bf16 hi/lo tiles
__global__ __launch_bounds__(256) void transpose_split_tiled(
    const float* __restrict__ W, unsigned char* __restrict__ Bt,
    int K, int N, int noff)
{
    __shared__ float tile[32][33];
    const int n0 = blockIdx.x * 32, k0 = blockIdx.y * 32;
    const int tx = threadIdx.x, ty = threadIdx.y;
#pragma unroll
    for (int i = 0; i < 32; i += 8)
        tile[ty + i][tx] = W[(size_t)(k0 + ty + i) * N + n0 + tx];
    __syncthreads();
#pragma unroll
    for (int i = 0; i < 32; i += 8) {
        float v = tile[tx][ty + i];
        __nv_bfloat16 h = __float2bfloat16_rn(v);
        __nv_bfloat16 l = __float2bfloat16_rn(v - __bfloat162float(h));
        int n = noff + n0 + ty + i;
        int k = k0 + tx;
        int nblk = n >> 8, row = n & 255, kt = k >> 5, c = k & 31;
        unsigned char* tb = Bt + ((size_t)nblk * (K >> 5) + kt) * 32768;
        *(__nv_bfloat16*)(tb + SMEM_SW128((uint32_t)(row * 128 + c * 2))) = h;
        *(__nv_bfloat16*)(tb + SMEM_SW128((uint32_t)(row * 128 + 64 + c * 2))) = l;
    }
}

__global__ __launch_bounds__(256) void v_split_t(
    const float* __restrict__ v, __nv_bfloat16* __restrict__ vth,
    __nv_bfloat16* __restrict__ vtl)
{
    __shared__ float tile[32][33];
    const int t0 = blockIdx.x * 32, d0 = blockIdx.y * 32;
    const int bkk = blockIdx.z;
    const int bb = bkk >> 3, kvh = bkk & 7;
    const int tx = threadIdx.x, ty = threadIdx.y;
#pragma unroll
    for (int i = 0; i < 32; i += 8)
        tile[ty + i][tx] = v[(size_t)(bb * Sn + t0 + ty + i) * KVD + kvh * HD + d0 + tx];
    __syncthreads();
#pragma unroll
    for (int i = 0; i < 32; i += 8) {
        float x = tile[tx][ty + i];
        __nv_bfloat16 h = __float2bfloat16_rn(x);
        size_t idx = (size_t)bkk * HD * Sn + (size_t)(d0 + ty + i) * Sn + t0 + tx;
        vth[idx] = h;
        vtl[idx] = __float2bfloat16_rn(x - __bfloat162float(h));
    }
}

__global__ __launch_bounds__(256) void rope_split(
    const float* __restrict__ q, const float* __restrict__ k,
    __nv_bfloat16* __restrict__ qsh, __nv_bfloat16* __restrict__ qsl,
    __nv_bfloat16* __restrict__ ksh, __nv_bfloat16* __restrict__ ksl,
    const int* __restrict__ pos_ids)
{
    const int tok = blockIdx.x;
    __shared__ float cs[64], sn[64];
    const int tid = threadIdx.x;
    const float pos = (float)pos_ids[tok];
    const float SCALE = 0.08838834764831845f;
    if (tid < 64) {
        float inv = powf(1.0e6f, -((float)tid) / 64.0f);
        sincosf(pos * inv, &sn[tid], &cs[tid]);
    }
    __syncthreads();
    for (int p = tid; p < (Hq + KVH) * 64; p += 256) {
        int head = p >> 6, i = p & 63;
        float c = cs[i], s = sn[i];
        if (head < Hq) {
            size_t base = (size_t)tok * DM + head * HD;
            float x1 = q[base + i], x2 = q[base + i + 64];
            float y1 = (x1 * c - x2 * s) * SCALE;
            float y2 = (x2 * c + x1 * s) * SCALE;
            __nv_bfloat16 h1 = __float2bfloat16_rn(y1);
            __nv_bfloat16 h2 = __float2bfloat16_rn(y2);
            qsh[base + i] = h1;
            qsh[base + i + 64] = h2;
            qsl[base + i] = __float2bfloat16_rn(y1 - __bfloat162float(h1));
            qsl[base + i + 64] = __float2bfloat16_rn(y2 - __bfloat162float(h2));
        } else {
            size_t base = (size_t)tok * KVD + (head - Hq) * HD;
            float x1 = k[base + i], x2 = k[base + i + 64];
            float y1 = x1 * c - x2 * s;
            float y2 = x2 * c + x1 * s;
            __nv_bfloat16 h1 = __float2bfloat16_rn(y1);
            __nv_bfloat16 h2 = __float2bfloat16_rn(y2);
            ksh[base + i] = h1;
            ksh[base + i + 64] = h2;
            ksl[base + i] = __float2bfloat16_rn(y1 - __bfloat162float(h1));
            ksl[base + i + 64] = __float2bfloat16_rn(y2 - __bfloat162float(h2));
        }
    }
}

// ---------------------------------------------------------------------------
extern "C" void kernel_launch(void* const* d_in, const int* in_sizes, int n_in,
                              void* d_out, int out_size)
{
    const float* hidden = (const float*)d_in[0];
    const float* Wq = (const float*)d_in[1];
    const float* Wk = (const float*)d_in[2];
    const float* Wv = (const float*)d_in[3];
    const float* Wo = (const float*)d_in[4];
    const int* pos_ids = (const int*)d_in[8];
    float* out = (float*)d_out;

    float *qp, *kp, *vp;
    __nv_bfloat16 *ahi, *alo, *qsh, *qsl, *ksh, *ksl, *vth, *vtl, *oh, *ol;
    unsigned char *wqt, *wkvt, *wot;
    cudaGetSymbolAddress((void**)&qp, g_q);
    cudaGetSymbolAddress((void**)&kp, g_k);
    cudaGetSymbolAddress((void**)&vp, g_v);
    cudaGetSymbolAddress((void**)&ahi, g_a_hi);
    cudaGetSymbolAddress((void**)&alo, g_a_lo);
    cudaGetSymbolAddress((void**)&wqt, g_wq_t);
    cudaGetSymbolAddress((void**)&wkvt, g_wkv_t);
    cudaGetSymbolAddress((void**)&wot, g_wo_t);
    cudaGetSymbolAddress((void**)&qsh, g_qs_hi);
    cudaGetSymbolAddress((void**)&qsl, g_qs_lo);
    cudaGetSymbolAddress((void**)&ksh, g_ks_hi);
    cudaGetSymbolAddress((void**)&ksl, g_ks_lo);
    cudaGetSymbolAddress((void**)&vth, g_vt_hi);
    cudaGetSymbolAddress((void**)&vtl, g_vt_lo);
    cudaGetSymbolAddress((void**)&oh, g_o_hi);
    cudaGetSymbolAddress((void**)&ol, g_o_lo);

    cudaFuncSetAttribute(tc_gemm, cudaFuncAttributeMaxDynamicSharedMemorySize, G_DYN);
    cudaFuncSetAttribute(tc_attn, cudaFuncAttributeMaxDynamicSharedMemorySize, AT_DYN);

    // pre-pass
    convert_split<<<(NTOK * DM / 4) / 256, 256>>>(hidden, ahi, alo, NTOK * DM / 4);
    transpose_split_tiled<<<dim3(DM / 32, DM / 32), dim3(32, 8)>>>(Wq, wqt, DM, DM, 0);
    transpose_split_tiled<<<dim3(KVD / 32, DM / 32), dim3(32, 8)>>>(Wk, wkvt, DM, KVD, 0);
    transpose_split_tiled<<<dim3(KVD / 32, DM / 32), dim3(32, 8)>>>(Wv, wkvt, DM, KVD, KVD);
    transpose_split_tiled<<<dim3(DM / 32, DM / 32), dim3(32, 8)>>>(Wo, wot, DM, DM, 0);

    // projections (B via single bulk copy per stage)
    tc_gemm<<<dim3(DM / 256, NTOK / 256), 256, G_DYN>>>(
        ahi, alo, wqt, qp, qp, DM, DM, DM);
    tc_gemm<<<dim3(2 * KVD / 256, NTOK / 256), 256, G_DYN>>>(
        ahi, alo, wkvt, kp, vp, KVD, KVD, DM);

    // rope + attention operand prep
    rope_split<<<NTOK, 256>>>(qp, kp, qsh, qsl, ksh, ksl, pos_ids);
    v_split_t<<<dim3(Sn / 32, HD / 32, Bn * KVH), dim3(32, 8)>>>(vp, vth, vtl);

    // attention
    tc_attn<<<dim3(Sn / 64, KVH, Bn), 256, AT_DYN>>>(
        qsh, qsl, ksh, ksl, vth, vtl, oh, ol);

    // output projection
    tc_gemm<<<dim3(DM / 256, NTOK / 256), 256, G_DYN>>>(
        oh, ol, wot, out, out, DM, DM, DM);
}

// round 14
// speedup vs baseline: 1.0774x; 1.0234x over previous
#include <cuda_runtime.h>
#include <cuda_bf16.h>
#include <math.h>
#include <stdint.h>

#define Hq 32
#define KVH 8
#define HD 128
#define Bn 4
#define Sn 1024
#define DM 4096
#define KVD 1024
#define NTOK (Bn*Sn)
#define WINDOW 512
#define NQKV (DM + 2*KVD)    // 6144
#define KVLD (2*KVD)         // 2048

#if defined(__CUDA_ARCH_FEAT_SM103_ALL) || defined(__CUDA_ARCH_FEAT_SM100_ALL)
#define TC_FEAT 1
#else
#define TC_FEAT 0
#endif

// Scratch
__device__ float g_q[NTOK * DM];
__device__ float g_kv[NTOK * KVLD];               // [tok][K 0..1023 | V 1024..2047]
__device__ __nv_bfloat16 g_a_hi[NTOK * DM];
__device__ __nv_bfloat16 g_a_lo[NTOK * DM];
__device__ __nv_bfloat16 g_wqkv_hi[NQKV * DM];    // rows: Wq^T | Wk^T | Wv^T (K-major)
__device__ __nv_bfloat16 g_wqkv_lo[NQKV * DM];
__device__ __nv_bfloat16 g_wo_hi[DM * DM];
__device__ __nv_bfloat16 g_wo_lo[DM * DM];
__device__ __nv_bfloat16 g_qs_hi[NTOK * DM];
__device__ __nv_bfloat16 g_qs_lo[NTOK * DM];
__device__ __nv_bfloat16 g_ks_hi[NTOK * KVD];
__device__ __nv_bfloat16 g_ks_lo[NTOK * KVD];
__device__ __nv_bfloat16 g_vt_hi[NTOK * KVD];
__device__ __nv_bfloat16 g_vt_lo[NTOK * KVD];
__device__ __nv_bfloat16 g_o_hi[NTOK * DM];
__device__ __nv_bfloat16 g_o_lo[NTOK * DM];

__device__ __forceinline__ uint32_t smem_u32(const void* p) {
    uint32_t a;
    asm("{ .reg .u64 t; cvta.to.shared.u64 t, %1; cvt.u32.u64 %0, t; }"
        : "=r"(a) : "l"(p));
    return a;
}
__device__ __forceinline__ uint32_t elect_one() {
    uint32_t pred;
    asm volatile("{\n .reg .pred p;\n elect.sync _|p, 0xFFFFFFFF;\n"
                 " selp.b32 %0, 1, 0, p;\n}" : "=r"(pred));
    return pred;
}
#define SMEM_SW128(off) ((off) ^ (((off) >> 3) & 0x70))
static constexpr uint64_t DESC_BASE_SW128 =
    (uint64_t(2) << 61) | (uint64_t(1) << 46) | (uint64_t(64) << 32) |
    (uint64_t(1) << 16);
__device__ __forceinline__ uint64_t make_desc(uint32_t addr) {
    return DESC_BASE_SW128 | ((uint64_t)(addr >> 4) & 0x3FFF);
}
#define MBAR_INIT(a, n) \
    asm volatile("mbarrier.init.shared.b64 [%0], %1;" :: "r"(a), "r"(n) : "memory")
#define MBAR_INVAL(a) \
    asm volatile("mbarrier.inval.shared.b64 [%0];" :: "r"(a) : "memory")
__device__ __forceinline__ void mbar_wait(uint32_t mbar, uint32_t parity) {
    uint32_t done;
    asm volatile("{\n\t.reg .pred p;\n\t"
        "mbarrier.try_wait.parity.acquire.cta.shared::cta.b64 p, [%1], %2;\n\t"
        "selp.b32 %0, 1, 0, p;\n\t}" : "=r"(done) : "r"(mbar), "r"(parity) : "memory");
    while (!done) {
        asm volatile("{\n\t.reg .pred p;\n\t"
            "mbarrier.try_wait.parity.acquire.cta.shared::cta.b64 p, [%1], %2, 0x989680;\n\t"
            "selp.b32 %0, 1, 0, p;\n\t}" : "=r"(done) : "r"(mbar), "r"(parity) : "memory");
    }
}
#define CP_ASYNC16(dst, src) \
    asm volatile("cp.async.cg.shared.global [%0], [%1], 16;" :: "r"(dst), "l"(src))
#define CP_COMMIT() asm volatile("cp.async.commit_group;" ::: "memory")
#define CP_WAIT0()  asm volatile("cp.async.wait_group 0;" ::: "memory")
#define CP_WAIT1()  asm volatile("cp.async.wait_group 1;" ::: "memory")

#if TC_FEAT
__device__ __forceinline__ void mma_bf16_ss(
    uint32_t d_tmem, uint64_t a_desc, uint64_t b_desc, uint32_t idesc, bool acc)
{
    uint32_t en = acc ? 1u : 0u;
    asm volatile(
        "{\n\t.reg .pred p;\n\tsetp.ne.u32 p, %4, 0;\n\t"
        "tcgen05.mma.cta_group::1.kind::f16 [%0], %1, %2, %3, {%5,%5,%5,%5}, p;\n\t}"
        :: "r"(d_tmem), "l"(a_desc), "l"(b_desc), "r"(idesc), "r"(en), "r"(0u)
        : "memory");
}
#define TC_ALLOC(a, n) \
    asm volatile("tcgen05.alloc.cta_group::1.sync.aligned.shared::cta.b32 [%0], %1;" \
                 :: "r"(a), "r"((uint32_t)(n)) : "memory")
#define TC_DEALLOC(t, n) \
    asm volatile("tcgen05.dealloc.cta_group::1.sync.aligned.b32 %0, %1;" \
                 :: "r"(t), "r"((uint32_t)(n)))
#define TC_RELINQ() \
    asm volatile("tcgen05.relinquish_alloc_permit.cta_group::1.sync.aligned;")
#define TC_COMMIT(m) \
    asm volatile("tcgen05.commit.cta_group::1.mbarrier::arrive::one.shared::cluster.b64 [%0];" \
                 :: "r"(m) : "memory")
#define TC_FENCE_AFTER() asm volatile("tcgen05.fence::after_thread_sync;" ::: "memory")
#define FENCE_ASYNC_SHARED() asm volatile("fence.proxy.async.shared::cta;" ::: "memory")
#define TC_LD_X32(r, addr) \
    asm volatile("tcgen05.ld.sync.aligned.32x32b.x32.b32 " \
        "{%0,%1,%2,%3,%4,%5,%6,%7,%8,%9,%10,%11,%12,%13,%14,%15," \
        "%16,%17,%18,%19,%20,%21,%22,%23,%24,%25,%26,%27,%28,%29,%30,%31}, [%32];" \
        : "=r"((r)[0]), "=r"((r)[1]), "=r"((r)[2]), "=r"((r)[3]), \
          "=r"((r)[4]), "=r"((r)[5]), "=r"((r)[6]), "=r"((r)[7]), \
          "=r"((r)[8]), "=r"((r)[9]), "=r"((r)[10]), "=r"((r)[11]), \
          "=r"((r)[12]), "=r"((r)[13]), "=r"((r)[14]), "=r"((r)[15]), \
          "=r"((r)[16]), "=r"((r)[17]), "=r"((r)[18]), "=r"((r)[19]), \
          "=r"((r)[20]), "=r"((r)[21]), "=r"((r)[22]), "=r"((r)[23]), \
          "=r"((r)[24]), "=r"((r)[25]), "=r"((r)[26]), "=r"((r)[27]), \
          "=r"((r)[28]), "=r"((r)[29]), "=r"((r)[30]), "=r"((r)[31]) \
        : "r"(addr))
#define TC_WAIT_LD() asm volatile("tcgen05.wait::ld.sync.aligned;" ::: "memory")

__device__ __forceinline__ void split2(float a, float b, uint32_t& hw, uint32_t& lw) {
    __nv_bfloat16 ha = __float2bfloat16_rn(a);
    __nv_bfloat16 hb = __float2bfloat16_rn(b);
    __nv_bfloat16 la = __float2bfloat16_rn(a - __bfloat162float(ha));
    __nv_bfloat16 lb = __float2bfloat16_rn(b - __bfloat162float(hb));
    hw = ((uint32_t)__bfloat16_as_ushort(hb) << 16) | (uint32_t)__bfloat16_as_ushort(ha);
    lw = ((uint32_t)__bfloat16_as_ushort(lb) << 16) | (uint32_t)__bfloat16_as_ushort(la);
}
#endif

// ---------------------------------------------------------------------------
// tcgen05 GEMM (R8-proven): 256x256 tile, K-tile 32, 3-stage cp.async,
// MMA-first ordering. Output: n0 < nsplit -> C (ldc), else C2 (ldc2).
// ---------------------------------------------------------------------------
#define TCG_OFF_B 32768
#define G_STAGE   65536
#define G_MBAR    (3 * G_STAGE)
#define G_TPTR    (3 * G_STAGE + 32)
#define G_DYN     (3 * G_STAGE + 64 + 1024)
#define G_IDESC   ((1u<<4)|(1u<<7)|(1u<<10)|(32u<<17)|(8u<<24))   // N=256

__global__ __launch_bounds__(256, 1) void tc_gemm(
    const __nv_bfloat16* __restrict__ Ahi, const __nv_bfloat16* __restrict__ Alo,
    const __nv_bfloat16* __restrict__ Bhi, const __nv_bfloat16* __restrict__ Blo,
    float* __restrict__ C, float* __restrict__ C2,
    int ldc, int ldc2, int nsplit, int K)
{
#if TC_FEAT
    extern __shared__ char dsm[];
    char* smb = (char*)(((uintptr_t)dsm + 1023) & ~(uintptr_t)1023);
    const uint32_t smb_u = smem_u32(smb);
    const int tid = threadIdx.x;
    const int wid = tid >> 5;
    const int lane = tid & 31;
    const int m0 = blockIdx.y * 256;
    const int n0 = blockIdx.x * 256;

    if (wid == 0) TC_ALLOC(smb_u + G_TPTR, 512);
    if (tid == 0) {
        MBAR_INIT(smb_u + G_MBAR + 0, 1);
        MBAR_INIT(smb_u + G_MBAR + 8, 1);
        MBAR_INIT(smb_u + G_MBAR + 16, 1);
    }
    __syncthreads();
    uint32_t tmem;
    asm volatile("ld.shared.b32 %0, [%1];" : "=r"(tmem) : "r"(smb_u + G_TPTR));

    const int T = K >> 5;
    auto stage = [&](int t) {
        const uint32_t sbase = smb_u + (t % 3) * G_STAGE;
        const int k0 = t * 32;
#pragma unroll
        for (int r = 0; r < 8; ++r) {
            int i = tid + r * 256;
            int row = i >> 3, c = i & 7;
            uint32_t dst = sbase + SMEM_SW128((uint32_t)(row * 128 + c * 16));
            const __nv_bfloat16* src = ((c & 4) ? Alo : Ahi)
                + (size_t)(m0 + row) * K + k0 + (c & 3) * 8;
            CP_ASYNC16(dst, src);
        }
#pragma unroll
        for (int r = 0; r < 8; ++r) {
            int i = tid + r * 256;
            int row = i >> 3, c = i & 7;
            uint32_t dst = sbase + TCG_OFF_B + SMEM_SW128((uint32_t)(row * 128 + c * 16));
            const __nv_bfloat16* src = ((c & 4) ? Blo : Bhi)
                + (size_t)(n0 + row) * K + k0 + (c & 3) * 8;
            CP_ASYNC16(dst, src);
        }
        CP_COMMIT();
    };

    stage(0);
    stage(1);
    for (int t = 0; t < T; ++t) {
        if (t < T - 1) { CP_WAIT1(); } else { CP_WAIT0(); }
        FENCE_ASYNC_SHARED();
        __syncthreads();

        if (wid == 0 && elect_one()) {
            const uint32_t sbase = smb_u + (t % 3) * G_STAGE;
            uint64_t da = make_desc(sbase);
            uint64_t db = make_desc(sbase + TCG_OFF_B);
#pragma unroll
            for (int k = 0; k < 2; ++k)
#pragma unroll
                for (int m = 0; m < 2; ++m) {
                    uint32_t d = tmem + m * 256;
                    uint64_t ao = (uint64_t)(m * 1024);
                    bool first = (t == 0) && (k == 0);
                    mma_bf16_ss(d, da + ao + k * 2,     db + k * 2,     G_IDESC, !first);
                    mma_bf16_ss(d, da + ao + k * 2,     db + 4 + k * 2, G_IDESC, true);
                    mma_bf16_ss(d, da + ao + 4 + k * 2, db + k * 2,     G_IDESC, true);
                }
            TC_COMMIT(smb_u + G_MBAR + 8 * (t % 3));
        }

        if (t + 2 < T) {
            if (t >= 1)
                mbar_wait(smb_u + G_MBAR + 8 * ((t + 2) % 3),
                          (uint32_t)(((t - 1) / 3) & 1));
            stage(t + 2);
        }
    }
#pragma unroll
    for (int i = 0; i < 3; ++i) {
        int cnt = (T + 2 - i) / 3;
        if (cnt > 0) mbar_wait(smb_u + G_MBAR + 8 * i, (uint32_t)((cnt - 1) & 1));
    }
    TC_FENCE_AFTER();

    {
        const int half = wid >> 2;
        const int mloc = (wid & 3) * 32 + lane;
        float* base;
        int col, ld;
        if (n0 < nsplit) { base = C;  col = n0;          ld = ldc;  }
        else             { base = C2; col = n0 - nsplit; ld = ldc2; }
        float* crow = base + (size_t)(m0 + half * 128 + mloc) * ld + col;
        uint32_t regs[32];
#pragma unroll
        for (int c = 0; c < 8; ++c) {
            TC_LD_X32(regs, tmem + half * 256 + c * 32);
            TC_WAIT_LD();
#pragma unroll
            for (int i = 0; i < 8; ++i)
                *(float4*)(crow + c * 32 + 4 * i) = make_float4(
                    __uint_as_float(regs[4*i]), __uint_as_float(regs[4*i+1]),
                    __uint_as_float(regs[4*i+2]), __uint_as_float(regs[4*i+3]));
        }
    }
    __syncthreads();
    if (tid == 0) {
        MBAR_INVAL(smb_u + G_MBAR + 0);
        MBAR_INVAL(smb_u + G_MBAR + 8);
        MBAR_INVAL(smb_u + G_MBAR + 16);
    }
    __syncthreads();
    if (wid == 0) { TC_RELINQ(); TC_DEALLOC(tmem, 512); }
#endif
}

// ---------------------------------------------------------------------------
// tcgen05 attention (byte-identical to R8's 970us version).
// ---------------------------------------------------------------------------
#define AT_Q     0
#define AT_KP    131072
#define AT_V     196608
#define AT_MBAR  229376
#define AT_TPTR  229408
#define AT_DYN   (229440 + 1024)
#define IDESC_S  ((1u<<4)|(1u<<7)|(1u<<10)|(8u<<17)|(8u<<24))
#define IDESC_O  ((1u<<4)|(1u<<7)|(1u<<10)|(16u<<17)|(8u<<24))
#define SMAX_C   12.0f

__global__ __launch_bounds__(256, 1) void tc_attn(
    const __nv_bfloat16* __restrict__ qsh, const __nv_bfloat16* __restrict__ qsl,
    const __nv_bfloat16* __restrict__ ksh, const __nv_bfloat16* __restrict__ ksl,
    const __nv_bfloat16* __restrict__ vth, const __nv_bfloat16* __restrict__ vtl,
    __nv_bfloat16* __restrict__ ohi, __nv_bfloat16* __restrict__ olo)
{
#if TC_FEAT
    extern __shared__ char dsm[];
    char* smb = (char*)(((uintptr_t)dsm + 1023) & ~(uintptr_t)1023);
    const uint32_t smb_u = smem_u32(smb);
    const uint32_t mbar_s = smb_u + AT_MBAR;
    const uint32_t mbar_o = smb_u + AT_MBAR + 8;
    const int tid = threadIdx.x;
    const int wid = tid >> 5;
    const int q0 = (int)(gridDim.x - 1 - blockIdx.x) * 64;
    const int kvh = blockIdx.y;
    const int b = blockIdx.z;
    const int bk = b * KVH + kvh;

    if (wid == 0) TC_ALLOC(smb_u + AT_TPTR, 512);
    if (tid == 0) { MBAR_INIT(mbar_s, 1); MBAR_INIT(mbar_o, 1); }
    __syncthreads();
    uint32_t tmem;
    asm volatile("ld.shared.b32 %0, [%1];" : "=r"(tmem) : "r"(smb_u + AT_TPTR));
    const uint32_t tmS = tmem;
    const uint32_t tmO = tmem + 128;

#pragma unroll
    for (int r = 0; r < 32; ++r) {
        int u = tid + r * 256;
        int row = u >> 5, cc = u & 31;
        int s = cc >> 4, hh = (cc >> 3) & 1, c = cc & 7;
        uint32_t byte = (uint32_t)(((row >> 3) + (s * 2 + hh) * 32) * 1024 +
                                   (row & 7) * 128 + c * 16);
        int tok = b * Sn + q0 + (row & 63);
        int head = kvh * 4 + (row >> 6);
        const __nv_bfloat16* src = (s ? qsl : qsh)
            + (size_t)tok * DM + head * HD + hh * 64 + c * 8;
        CP_ASYNC16(smb_u + AT_Q + SMEM_SW128(byte), src);
    }
    CP_COMMIT();

    const int kc0 = (q0 >= WINDOW) ? (q0 - WINDOW) : 0;
    const int nch = (q0 - kc0) / 64 + 1;
    float l_i = 0.f;
    uint32_t ps = 0, po = 0;
    const int atom = wid >> 2;
    const int grow = tid;
    const int qi = q0 + (grow & 63);

    for (int ci = 0; ci < nch; ++ci) {
        const int kc = kc0 + ci * 64;
        if (ci > 0) { mbar_wait(mbar_o, po); po ^= 1; }

#pragma unroll
        for (int r = 0; r < 8; ++r) {
            int u = tid + r * 256;
            int key = u >> 5, cc = u & 31;
            int s = cc >> 4, hh = (cc >> 3) & 1, c = cc & 7;
            uint32_t byte = (uint32_t)(((key >> 3) + (s * 2 + hh) * 8) * 1024 +
                                       (key & 7) * 128 + c * 16);
            const __nv_bfloat16* src = (s ? ksl : ksh)
                + (size_t)(b * Sn + kc + key) * KVD + kvh * HD + hh * 64 + c * 8;
            CP_ASYNC16(smb_u + AT_KP + SMEM_SW128(byte), src);
        }
        CP_COMMIT();
#pragma unroll
        for (int r = 0; r < 8; ++r) {
            int u = tid + r * 256;
            int d = u >> 4, cc = u & 15;
            int s = cc >> 3, c = cc & 7;
            uint32_t byte = (uint32_t)(((d >> 3) + s * 16) * 1024 +
                                       (d & 7) * 128 + c * 16);
            const __nv_bfloat16* src = (s ? vtl : vth)
                + (size_t)bk * HD * Sn + (size_t)d * Sn + kc + c * 8;
            CP_ASYNC16(smb_u + AT_V + SMEM_SW128(byte), src);
        }
        CP_COMMIT();
        CP_WAIT1();
        FENCE_ASYNC_SHARED();
        __syncthreads();

        if (wid == 0 && elect_one()) {
            uint64_t dq = make_desc(smb_u + AT_Q);
            uint64_t dk = make_desc(smb_u + AT_KP);
#pragma unroll
            for (int m = 0; m < 2; ++m)
#pragma unroll
                for (int pat = 0; pat < 3; ++pat) {
                    int sa = (pat == 2), sb = (pat == 1);
#pragma unroll
                    for (int k = 0; k < 8; ++k) {
                        uint64_t qo = (uint64_t)(m * 1024 +
                                      (sa * 2 + (k >> 2)) * 2048 + (k & 3) * 2);
                        uint64_t ko = (uint64_t)((sb * 2 + (k >> 2)) * 512 + (k & 3) * 2);
                        mma_bf16_ss(tmS + m * 64, dq + qo, dk + ko, IDESC_S,
                                    !(pat == 0 && k == 0));
                    }
                }
            TC_COMMIT(mbar_s);
        }

        mbar_wait(mbar_s, ps);
        ps ^= 1;
        TC_FENCE_AFTER();
        uint32_t su[64];
        TC_LD_X32(su, tmS + atom * 64);
        TC_LD_X32(su + 32, tmS + atom * 64 + 32);
        TC_WAIT_LD();
        float l_add = 0.f;
#pragma unroll
        for (int c16 = 0; c16 < 8; ++c16) {
            uint32_t wh[4], wl[4];
#pragma unroll
            for (int e = 0; e < 4; ++e) {
                int i0 = c16 * 8 + e * 2;
                int j0 = kc + i0;
                float s0 = __uint_as_float(su[i0]);
                float s1 = __uint_as_float(su[i0 + 1]);
                float p0 = ((j0 <= qi) && (j0 > qi - WINDOW)) ? __expf(s0 - SMAX_C) : 0.f;
                float p1 = ((j0+1 <= qi) && (j0+1 > qi - WINDOW)) ? __expf(s1 - SMAX_C) : 0.f;
                l_add += p0 + p1;
                split2(p0, p1, wh[e], wl[e]);
            }
            uint32_t bh = (uint32_t)((grow >> 3) * 1024 + (grow & 7) * 128 + c16 * 16);
            uint32_t bl = bh + 32 * 1024;
            *(uint4*)(smb + AT_KP + SMEM_SW128(bh)) = make_uint4(wh[0], wh[1], wh[2], wh[3]);
            *(uint4*)(smb + AT_KP + SMEM_SW128(bl)) = make_uint4(wl[0], wl[1], wl[2], wl[3]);
        }
        l_i += l_add;
        CP_WAIT0();
        FENCE_ASYNC_SHARED();
        __syncthreads();

        if (wid == 0 && elect_one()) {
            uint64_t dp = make_desc(smb_u + AT_KP);
            uint64_t dv = make_desc(smb_u + AT_V);
#pragma unroll
            for (int m = 0; m < 2; ++m)
#pragma unroll
                for (int pat = 0; pat < 3; ++pat) {
                    int sp = (pat == 2), sv = (pat == 1);
#pragma unroll
                    for (int k = 0; k < 4; ++k) {
                        uint64_t pofs = (uint64_t)(m * 1024 + sp * 2048 + k * 2);
                        uint64_t vofs = (uint64_t)(sv * 1024 + k * 2);
                        mma_bf16_ss(tmO + m * 128, dp + pofs, dv + vofs, IDESC_O,
                                    !(ci == 0 && pat == 0 && k == 0));
                    }
                }
            TC_COMMIT(mbar_o);
        }
        __syncthreads();
    }

    mbar_wait(mbar_o, po);
    TC_FENCE_AFTER();

    {
        const float inv = 1.0f / l_i;
        const int tok = b * Sn + q0 + (grow & 63);
        const int head = kvh * 4 + (grow >> 6);
        __nv_bfloat16* bh = ohi + (size_t)tok * DM + head * HD;
        __nv_bfloat16* bl = olo + (size_t)tok * DM + head * HD;
#pragma unroll
        for (int c = 0; c < 4; ++c) {
            uint32_t ov[32];
            TC_LD_X32(ov, tmO + atom * 128 + c * 32);
            TC_WAIT_LD();
#pragma unroll
            for (int g = 0; g < 4; ++g) {
                uint32_t ph[4], pl[4];
#pragma unroll
                for (int e = 0; e < 4; ++e) {
                    float v0 = __uint_as_float(ov[g*8 + e*2]) * inv;
                    float v1 = __uint_as_float(ov[g*8 + e*2 + 1]) * inv;
                    split2(v0, v1, ph[e], pl[e]);
                }
                *(uint4*)(bh + c * 32 + g * 8) = make_uint4(ph[0], ph[1], ph[2], ph[3]);
                *(uint4*)(bl + c * 32 + g * 8) = make_uint4(pl[0], pl[1], pl[2], pl[3]);
            }
        }
    }
    __syncthreads();
    if (tid == 0) { MBAR_INVAL(mbar_s); MBAR_INVAL(mbar_o); }
    __syncthreads();
    if (wid == 0) { TC_RELINQ(); TC_DEALLOC(tmem, 512); }
#endif
}

// ---------------------------------------------------------------------------
// Pre-pass kernels
// ---------------------------------------------------------------------------
__global__ __launch_bounds__(256) void convert_split(
    const float* __restrict__ x, __nv_bfloat16* __restrict__ hi,
    __nv_bfloat16* __restrict__ lo, int n4)
{
    int i = blockIdx.x * 256 + threadIdx.x;
    if (i >= n4) return;
    float4 v = ((const float4*)x)[i];
    __nv_bfloat16 h[4], l[4];
    float vv[4] = {v.x, v.y, v.z, v.w};
#pragma unroll
    for (int j = 0; j < 4; ++j) {
        h[j] = __float2bfloat16_rn(vv[j]);
        l[j] = __float2bfloat16_rn(vv[j] - __bfloat162float(h[j]));
    }
    ((uint64_t*)hi)[i] = *(uint64_t*)h;
    ((uint64_t*)lo)[i] = *(uint64_t*)l;
}

__global__ __launch_bounds__(256) void transpose_split(
    const float* __restrict__ W, __nv_bfloat16* __restrict__ Thi,
    __nv_bfloat16* __restrict__ Tlo, int K, int N, int noff)
{
    __shared__ float tile[32][33];
    const int n0 = blockIdx.x * 32, k0 = blockIdx.y * 32;
    const int tx = threadIdx.x, ty = threadIdx.y;
#pragma unroll
    for (int i = 0; i < 32; i += 8)
        tile[ty + i][tx] = W[(size_t)(k0 + ty + i) * N + n0 + tx];
    __syncthreads();
#pragma unroll
    for (int i = 0; i < 32; i += 8) {
        float v = tile[tx][ty + i];
        __nv_bfloat16 h = __float2bfloat16_rn(v);
        size_t idx = (size_t)(noff + n0 + ty + i) * K + k0 + tx;
        Thi[idx] = h;
        Tlo[idx] = __float2bfloat16_rn(v - __bfloat162float(h));
    }
}

// V part of g_kv [tok][1024 + kvh*128 + d] -> vt[bk][d][tok] hi/lo
__global__ __launch_bounds__(256) void v_split_t(
    const float* __restrict__ kv, __nv_bfloat16* __restrict__ vth,
    __nv_bfloat16* __restrict__ vtl)
{
    __shared__ float tile[32][33];
    const int t0 = blockIdx.x * 32, d0 = blockIdx.y * 32;
    const int bkk = blockIdx.z;
    const int bb = bkk >> 3, kvh = bkk & 7;
    const int tx = threadIdx.x, ty = threadIdx.y;
#pragma unroll
    for (int i = 0; i < 32; i += 8)
        tile[ty + i][tx] = kv[(size_t)(bb * Sn + t0 + ty + i) * KVLD +
                              KVD + kvh * HD + d0 + tx];
    __syncthreads();
#pragma unroll
    for (int i = 0; i < 32; i += 8) {
        float x = tile[tx][ty + i];
        __nv_bfloat16 h = __float2bfloat16_rn(x);
        size_t idx = (size_t)bkk * HD * Sn + (size_t)(d0 + ty + i) * Sn + t0 + tx;
        vth[idx] = h;
        vtl[idx] = __float2bfloat16_rn(x - __bfloat162float(h));
    }
}

// RoPE + split: q from g_q, k from g_kv (stride KVLD)
__global__ __launch_bounds__(256) void rope_split(
    const float* __restrict__ q, const float* __restrict__ kv,
    __nv_bfloat16* __restrict__ qsh, __nv_bfloat16* __restrict__ qsl,
    __nv_bfloat16* __restrict__ ksh, __nv_bfloat16* __restrict__ ksl,
    const int* __restrict__ pos_ids)
{
    const int tok = blockIdx.x;
    __shared__ float cs[64], sn[64];
    const int tid = threadIdx.x;
    const float pos = (float)pos_ids[tok];
    const float SCALE = 0.08838834764831845f;
    if (tid < 64) {
        float inv = powf(1.0e6f, -((float)tid) / 64.0f);
        sincosf(pos * inv, &sn[tid], &cs[tid]);
    }
    __syncthreads();
    for (int p = tid; p < (Hq + KVH) * 64; p += 256) {
        int head = p >> 6, i = p & 63;
        float c = cs[i], s = sn[i];
        if (head < Hq) {
            size_t base = (size_t)tok * DM + head * HD;
            float x1 = q[base + i], x2 = q[base + i + 64];
            float y1 = (x1 * c - x2 * s) * SCALE;
            float y2 = (x2 * c + x1 * s) * SCALE;
            __nv_bfloat16 h1 = __float2bfloat16_rn(y1);
            __nv_bfloat16 h2 = __float2bfloat16_rn(y2);
            qsh[base + i] = h1;
            qsh[base + i + 64] = h2;
            qsl[base + i] = __float2bfloat16_rn(y1 - __bfloat162float(h1));
            qsl[base + i + 64] = __float2bfloat16_rn(y2 - __bfloat162float(h2));
        } else {
            int kh = head - Hq;
            size_t sbase = (size_t)tok * KVLD + kh * HD;       // read from g_kv
            size_t dbase = (size_t)tok * KVD + kh * HD;        // write to ks
            float x1 = kv[sbase + i], x2 = kv[sbase + i + 64];
            float y1 = x1 * c - x2 * s;
            float y2 = x2 * c + x1 * s;
            __nv_bfloat16 h1 = __float2bfloat16_rn(y1);
            __nv_bfloat16 h2 = __float2bfloat16_rn(y2);
            ksh[dbase + i] = h1;
            ksh[dbase + i + 64] = h2;
            ksl[dbase + i] = __float2bfloat16_rn(y1 - __bfloat162float(h1));
            ksl[dbase + i + 64] = __float2bfloat16_rn(y2 - __bfloat162float(h2));
        }
    }
}

// ---------------------------------------------------------------------------
extern "C" void kernel_launch(void* const* d_in, const int* in_sizes, int n_in,
                              void* d_out, int out_size)
{
    const float* hidden = (const float*)d_in[0];
    const float* Wq = (const float*)d_in[1];
    const float* Wk = (const float*)d_in[2];
    const float* Wv = (const float*)d_in[3];
    const float* Wo = (const float*)d_in[4];
    const int* pos_ids = (const int*)d_in[8];
    float* out = (float*)d_out;

    float *qp, *kvp;
    __nv_bfloat16 *ahi, *alo, *wqkvh, *wqkvl, *woh, *wol;
    __nv_bfloat16 *qsh, *qsl, *ksh, *ksl, *vth, *vtl, *oh, *ol;
    cudaGetSymbolAddress((void**)&qp, g_q);
    cudaGetSymbolAddress((void**)&kvp, g_kv);
    cudaGetSymbolAddress((void**)&ahi, g_a_hi);
    cudaGetSymbolAddress((void**)&alo, g_a_lo);
    cudaGetSymbolAddress((void**)&wqkvh, g_wqkv_hi);
    cudaGetSymbolAddress((void**)&wqkvl, g_wqkv_lo);
    cudaGetSymbolAddress((void**)&woh, g_wo_hi);
    cudaGetSymbolAddress((void**)&wol, g_wo_lo);
    cudaGetSymbolAddress((void**)&qsh, g_qs_hi);
    cudaGetSymbolAddress((void**)&qsl, g_qs_lo);
    cudaGetSymbolAddress((void**)&ksh, g_ks_hi);
    cudaGetSymbolAddress((void**)&ksl, g_ks_lo);
    cudaGetSymbolAddress((void**)&vth, g_vt_hi);
    cudaGetSymbolAddress((void**)&vtl, g_vt_lo);
    cudaGetSymbolAddress((void**)&oh, g_o_hi);
    cudaGetSymbolAddress((void**)&ol, g_o_lo);

    cudaFuncSetAttribute(tc_gemm, cudaFuncAttributeMaxDynamicSharedMemorySize, G_DYN);
    cudaFuncSetAttribute(tc_attn, cudaFuncAttributeMaxDynamicSharedMemorySize, AT_DYN);

    // pre-pass
    convert_split<<<(NTOK * DM / 4) / 256, 256>>>(hidden, ahi, alo, NTOK * DM / 4);
    transpose_split<<<dim3(DM / 32, DM / 32), dim3(32, 8)>>>(Wq, wqkvh, wqkvl, DM, DM, 0);
    transpose_split<<<dim3(KVD / 32, DM / 32), dim3(32, 8)>>>(Wk, wqkvh, wqkvl, DM, KVD, DM);
    transpose_split<<<dim3(KVD / 32, DM / 32), dim3(32, 8)>>>(Wv, wqkvh, wqkvl, DM, KVD, DM + KVD);
    transpose_split<<<dim3(DM / 32, DM / 32), dim3(32, 8)>>>(Wo, woh, wol, DM, DM, 0);

    // merged QKV projection: N=6144, 384 CTAs; Q -> g_q, K|V -> g_kv
    tc_gemm<<<dim3(NQKV / 256, NTOK / 256), 256, G_DYN>>>(
        ahi, alo, wqkvh, wqkvl, qp, kvp, DM, KVLD, DM, DM);

    // rope + attention operand prep
    rope_split<<<NTOK, 256>>>(qp, kvp, qsh, qsl, ksh, ksl, pos_ids);
    v_split_t<<<dim3(Sn / 32, HD / 32, Bn * KVH), dim3(32, 8)>>>(kvp, vth, vtl);

    // attention
    tc_attn<<<dim3(Sn / 64, KVH, Bn), 256, AT_DYN>>>(
        qsh, qsl, ksh, ksl, vth, vtl, oh, ol);

    // output projection
    tc_gemm<<<dim3(DM / 256, NTOK / 256), 256, G_DYN>>>(
        oh, ol, woh, wol, out, out, DM, DM, DM, DM);
}